// round 10
// baseline (speedup 1.0000x reference)
#include <cuda_runtime.h>
#include <cstdint>
#include <math.h>

// ---------------- problem constants ----------------
#define NN      8192
#define FDIM    256
#define DSUB    64
#define KHOP    3
#define ODIM    128
#define COEFF   0.03125f           // d/(n*eps^2) = 64/(8192*0.25)
#define ETA_C   0.5f
#define LAPSC   0.15f              // ETA*LAMBDA_LAP
#define LN_EPSF 1e-5f

// ---------------- device scratch (no allocs allowed) ----------------
__device__ float g_Z[KHOP][NN][DSUB];           // 6.3 MB
__device__ float g_Gpart[KHOP][32][DSUB*DSUB];  // 1.6 MB
__device__ float g_R[KHOP];
__device__ float g_s[KHOP];                     // ETA*coeff*w[k]
__device__ float g_Lf[KHOP][DSUB*65];           // Chol factor, diag = 1/sqrt
__device__ float g_WWop[KHOP][4][DSUB][ODIM];   // partial W[k] @ Wout^T
__device__ float g_Bs[KHOP][DSUB][ODIM];        // s_k * M^{-1} WWo
__device__ float g_HW[NN*ODIM];                 // H @ Wout^T   (4 MB)
__device__ float g_LHWp[2][NN*ODIM];            // split-K partials of L @ HW (8 MB)

// ---------------- streams/events created at load time ----------------
struct StreamRes {
    cudaStream_t s2;
    cudaEvent_t evFork, evJoin;
    StreamRes() {
        cudaStreamCreateWithFlags(&s2, cudaStreamNonBlocking);
        cudaEventCreateWithFlags(&evFork, cudaEventDisableTiming);
        cudaEventCreateWithFlags(&evJoin, cudaEventDisableTiming);
    }
};
static StreamRes g_sr;

// ============================================================
// 1) HW = H @ Wout^T  [8192 x 128, K=256]
// ============================================================
__global__ __launch_bounds__(256) void computeHW(const float* __restrict__ H,
                                                 const float* __restrict__ Wout) {
    __shared__ float sAt[16][68];
    __shared__ float sB[16][132];
    const int tid = threadIdx.x;
    const int tx = tid & 15, ty = tid >> 4;
    const int r0 = blockIdx.x * 64;
    float acc[4][8] = {};

    for (int f0 = 0; f0 < FDIM; f0 += 16) {
        int ar = tid >> 2, ac = (tid & 3) * 4;
        float4 a = *(const float4*)&H[(size_t)(r0 + ar) * FDIM + f0 + ac];
        sAt[ac + 0][ar] = a.x; sAt[ac + 1][ar] = a.y;
        sAt[ac + 2][ar] = a.z; sAt[ac + 3][ar] = a.w;
        int bo = tid >> 1, bf = (tid & 1) * 8;
        const float* wpp = Wout + (size_t)bo * FDIM + f0 + bf;
        float4 b1 = *(const float4*)wpp;
        float4 b2 = *(const float4*)(wpp + 4);
        sB[bf + 0][bo] = b1.x; sB[bf + 1][bo] = b1.y;
        sB[bf + 2][bo] = b1.z; sB[bf + 3][bo] = b1.w;
        sB[bf + 4][bo] = b2.x; sB[bf + 5][bo] = b2.y;
        sB[bf + 6][bo] = b2.z; sB[bf + 7][bo] = b2.w;
        __syncthreads();
        #pragma unroll
        for (int kk = 0; kk < 16; kk++) {
            float ra[4], rb[8];
            *(float4*)&ra[0] = *(const float4*)&sAt[kk][ty * 4];
            *(float4*)&rb[0] = *(const float4*)&sB[kk][tx * 8];
            *(float4*)&rb[4] = *(const float4*)&sB[kk][tx * 8 + 4];
            #pragma unroll
            for (int i = 0; i < 4; i++)
                #pragma unroll
                for (int j = 0; j < 8; j++) acc[i][j] += ra[i] * rb[j];
        }
        __syncthreads();
    }
    #pragma unroll
    for (int i = 0; i < 4; i++) {
        size_t row = r0 + ty * 4 + i;
        *(float4*)&g_HW[row * ODIM + tx * 8]     = make_float4(acc[i][0], acc[i][1], acc[i][2], acc[i][3]);
        *(float4*)&g_HW[row * ODIM + tx * 8 + 4] = make_float4(acc[i][4], acc[i][5], acc[i][6], acc[i][7]);
    }
}

// ============================================================
// 2) Z[k] = hop_feats[k] @ W[k]^T
// ============================================================
__global__ __launch_bounds__(256) void compute_Z(const float* __restrict__ hop,
                                                 const float* __restrict__ Wst) {
    extern __shared__ float sm[];
    float* sH = sm;               // [64][257]
    float* sW = sm + 64 * 257;    // [64][257]
    const int tid = threadIdx.x;
    const int k = blockIdx.y;
    const int r0 = blockIdx.x * 64;

    const float* hp = hop + ((size_t)k * NN + r0) * FDIM;
    const float* wp = Wst + (size_t)k * DSUB * FDIM;
    for (int idx = tid * 4; idx < 64 * FDIM; idx += 1024) {
        int r = idx >> 8, c = idx & 255;
        float4 v = *(const float4*)(hp + idx);
        sH[r * 257 + c + 0] = v.x; sH[r * 257 + c + 1] = v.y;
        sH[r * 257 + c + 2] = v.z; sH[r * 257 + c + 3] = v.w;
        float4 w = *(const float4*)(wp + idx);
        sW[r * 257 + c + 0] = w.x; sW[r * 257 + c + 1] = w.y;
        sW[r * 257 + c + 2] = w.z; sW[r * 257 + c + 3] = w.w;
    }
    __syncthreads();

    const int tx = tid & 15, ty = tid >> 4;
    float acc[4][4] = {};
    #pragma unroll 4
    for (int f = 0; f < FDIM; f++) {
        float a[4], b[4];
        #pragma unroll
        for (int i = 0; i < 4; i++) a[i] = sH[(ty * 4 + i) * 257 + f];
        #pragma unroll
        for (int j = 0; j < 4; j++) b[j] = sW[(tx * 4 + j) * 257 + f];
        #pragma unroll
        for (int i = 0; i < 4; i++)
            #pragma unroll
            for (int j = 0; j < 4; j++) acc[i][j] += a[i] * b[j];
    }
    #pragma unroll
    for (int i = 0; i < 4; i++) {
        float4 o = make_float4(acc[i][0], acc[i][1], acc[i][2], acc[i][3]);
        *(float4*)&g_Z[k][r0 + ty * 4 + i][tx * 4] = o;
    }
}

// ============================================================
// 3) partial Gram: each block (32 per k) does 256 rows of Z^T Z
// ============================================================
__global__ __launch_bounds__(256) void compute_G(void) {
    __shared__ float sZ[16 * DSUB];
    const int tid = threadIdx.x;
    const int k = blockIdx.y;
    const int r0 = blockIdx.x * 256;
    const int tx = tid & 15, ty = tid >> 4;
    float acc[4][4] = {};

    for (int chunk = 0; chunk < 256; chunk += 16) {
        int lr = tid >> 4, lc = (tid & 15) * 4;
        *(float4*)&sZ[lr * DSUB + lc] = *(const float4*)&g_Z[k][r0 + chunk + lr][lc];
        __syncthreads();
        #pragma unroll
        for (int rr = 0; rr < 16; rr++) {
            float4 a = *(const float4*)&sZ[rr * DSUB + ty * 4];
            float4 b = *(const float4*)&sZ[rr * DSUB + tx * 4];
            float av[4] = {a.x, a.y, a.z, a.w};
            float bv[4] = {b.x, b.y, b.z, b.w};
            #pragma unroll
            for (int i = 0; i < 4; i++)
                #pragma unroll
                for (int j = 0; j < 4; j++) acc[i][j] += av[i] * bv[j];
        }
        __syncthreads();
    }
    #pragma unroll
    for (int i = 0; i < 4; i++)
        #pragma unroll
        for (int j = 0; j < 4; j++)
            g_Gpart[k][blockIdx.x][(ty * 4 + i) * DSUB + tx * 4 + j] = acc[i][j];
}

// ============================================================
// 4) LHWp[kh] = L[:, kh-half] @ HW[kh-half, :] ; tf32 mma + cp.async
// ============================================================
#define APAD 36
#define BPAD 136
#define ASTG (64 * APAD)               // 2304 floats (9216 B)
#define BSTG (32 * BPAD)               // 4352 floats (17408 B)
#define STGF (ASTG + BSTG)             // 6656 floats (26624 B)
#define NSTAGE 4
#define G2_SMEM (NSTAGE * STGF * 4)    // 106496 B
#define KHALF (NN / 2)                 // 4096

__device__ __forceinline__ void mma_tf32_16x8x8(float* c, const uint32_t* a,
                                                const uint32_t* b) {
    asm volatile(
        "mma.sync.aligned.m16n8k8.row.col.f32.tf32.tf32.f32 "
        "{%0,%1,%2,%3}, {%4,%5,%6,%7}, {%8,%9}, {%0,%1,%2,%3};"
        : "+f"(c[0]), "+f"(c[1]), "+f"(c[2]), "+f"(c[3])
        : "r"(a[0]), "r"(a[1]), "r"(a[2]), "r"(a[3]), "r"(b[0]), "r"(b[1]));
}

__global__ __launch_bounds__(256, 2) void gemmLHW(const float* __restrict__ L,
                                                  const float* __restrict__ HW,
                                                  float* __restrict__ LHWp) {
    extern __shared__ float smx[];
    uint32_t sb;
    asm("{ .reg .u64 t; cvta.to.shared.u64 t, %1; cvt.u32.u64 %0, t; }"
        : "=r"(sb) : "l"(smx));

    const int tid = threadIdx.x;
    const int lane = tid & 31;
    const int warp = tid >> 5;
    const int g = lane >> 2, t = lane & 3;
    const int wm = (warp & 1) * 32;
    const int wn = (warp >> 1) * 32;
    const int m0 = blockIdx.y * 64;
    const int kh = blockIdx.x;                    // 0 or 1
    const size_t koff = (size_t)kh * KHALF;

    const int ar0 = tid >> 3, ac0 = (tid & 7) * 4;   // A rows ar0, ar0+32
    const int br0 = tid >> 5, bc0 = (tid & 31) * 4;  // B rows br0+8q

    auto issue = [&](int stg) {
        const uint32_t st = sb + (uint32_t)(stg & (NSTAGE - 1)) * (STGF * 4);
        const float* As = L + (size_t)(m0 + ar0) * NN + koff + (size_t)stg * 32 + ac0;
        #pragma unroll
        for (int q = 0; q < 2; q++) {
            uint32_t d = st + (uint32_t)((ar0 + q * 32) * APAD + ac0) * 4u;
            asm volatile("cp.async.cg.shared.global [%0], [%1], 16;"
                         :: "r"(d), "l"(As + (size_t)q * 32 * NN) : "memory");
        }
        const float* Bs = HW + (koff + (size_t)stg * 32 + br0) * ODIM + bc0;
        const uint32_t bb = st + ASTG * 4u;
        #pragma unroll
        for (int q = 0; q < 4; q++) {
            uint32_t d = bb + (uint32_t)((br0 + q * 8) * BPAD + bc0) * 4u;
            asm volatile("cp.async.cg.shared.global [%0], [%1], 16;"
                         :: "r"(d), "l"(Bs + (size_t)q * 8 * ODIM) : "memory");
        }
    };

    #pragma unroll
    for (int s = 0; s < NSTAGE - 1; s++) {
        issue(s);
        asm volatile("cp.async.commit_group;" ::: "memory");
    }

    float acc[2][4][4] = {};
    const int NITER = KHALF / 32;   // 128

    for (int it = 0; it < NITER; it++) {
        asm volatile("cp.async.wait_group %0;" :: "n"(NSTAGE - 2) : "memory");
        __syncthreads();
        int nx = it + NSTAGE - 1;
        if (nx < NITER) issue(nx);
        asm volatile("cp.async.commit_group;" ::: "memory");

        const float* pa = smx + (it & (NSTAGE - 1)) * STGF;
        const float* pb = pa + ASTG;
        const uint32_t* ua = (const uint32_t*)pa;
        const uint32_t* ub = (const uint32_t*)pb;
        #pragma unroll
        for (int ks = 0; ks < 4; ks++) {
            const int kk = ks * 8 + t;
            uint32_t af[2][4], bf[4][2];
            #pragma unroll
            for (int mt = 0; mt < 2; mt++) {
                const int r = wm + mt * 16 + g;
                af[mt][0] = ua[r * APAD + kk];
                af[mt][1] = ua[(r + 8) * APAD + kk];
                af[mt][2] = ua[r * APAD + kk + 4];
                af[mt][3] = ua[(r + 8) * APAD + kk + 4];
            }
            #pragma unroll
            for (int nt = 0; nt < 4; nt++) {
                const int n = wn + nt * 8 + g;
                bf[nt][0] = ub[kk * BPAD + n];
                bf[nt][1] = ub[(kk + 4) * BPAD + n];
            }
            #pragma unroll
            for (int mt = 0; mt < 2; mt++)
                #pragma unroll
                for (int nt = 0; nt < 4; nt++)
                    mma_tf32_16x8x8(acc[mt][nt], af[mt], bf[nt]);
        }
    }

    float* outp = LHWp + (size_t)kh * NN * ODIM;
    const int er = g, ec = t * 2;
    #pragma unroll
    for (int mt = 0; mt < 2; mt++) {
        #pragma unroll
        for (int nt = 0; nt < 4; nt++) {
            const int row = m0 + wm + mt * 16 + er;
            const int col = wn + nt * 8 + ec;
            *(float2*)&outp[(size_t)row * ODIM + col] =
                make_float2(acc[mt][nt][0], acc[mt][nt][1]);
            *(float2*)&outp[(size_t)(row + 8) * ODIM + col] =
                make_float2(acc[mt][nt][2], acc[mt][nt][3]);
        }
    }
}

// ============================================================
// 5) WWo partials: grid (KHOP, 4); each CTA does 64 f-values
// ============================================================
__global__ __launch_bounds__(256) void computeWWo(const float* __restrict__ Wst,
                                                  const float* __restrict__ Wout) {
    __shared__ float sAt[16][68];
    __shared__ float sB[16][132];
    const int tid = threadIdx.x;
    const int tx = tid & 15, ty = tid >> 4;
    const int k = blockIdx.x;
    const int fbase = blockIdx.y * 64;
    float acc[4][8] = {};

    for (int fo = 0; fo < 64; fo += 16) {
        int f0 = fbase + fo;
        int ar = tid >> 2, ac = (tid & 3) * 4;
        float4 a = *(const float4*)&Wst[((size_t)k * DSUB + ar) * FDIM + f0 + ac];
        sAt[ac + 0][ar] = a.x; sAt[ac + 1][ar] = a.y;
        sAt[ac + 2][ar] = a.z; sAt[ac + 3][ar] = a.w;
        int bo = tid >> 1, bf = (tid & 1) * 8;
        const float* wpp = Wout + (size_t)bo * FDIM + f0 + bf;
        float4 b1 = *(const float4*)wpp;
        float4 b2 = *(const float4*)(wpp + 4);
        sB[bf + 0][bo] = b1.x; sB[bf + 1][bo] = b1.y;
        sB[bf + 2][bo] = b1.z; sB[bf + 3][bo] = b1.w;
        sB[bf + 4][bo] = b2.x; sB[bf + 5][bo] = b2.y;
        sB[bf + 6][bo] = b2.z; sB[bf + 7][bo] = b2.w;
        __syncthreads();
        #pragma unroll
        for (int kk = 0; kk < 16; kk++) {
            float ra[4], rb[8];
            *(float4*)&ra[0] = *(const float4*)&sAt[kk][ty * 4];
            *(float4*)&rb[0] = *(const float4*)&sB[kk][tx * 8];
            *(float4*)&rb[4] = *(const float4*)&sB[kk][tx * 8 + 4];
            #pragma unroll
            for (int i = 0; i < 4; i++)
                #pragma unroll
                for (int j = 0; j < 8; j++) acc[i][j] += ra[i] * rb[j];
        }
        __syncthreads();
    }
    #pragma unroll
    for (int i = 0; i < 4; i++) {
        int d = ty * 4 + i;
        *(float4*)&g_WWop[k][blockIdx.y][d][tx * 8]     = make_float4(acc[i][0], acc[i][1], acc[i][2], acc[i][3]);
        *(float4*)&g_WWop[k][blockIdx.y][d][tx * 8 + 4] = make_float4(acc[i][4], acc[i][5], acc[i][6], acc[i][7]);
    }
}

// ============================================================
// 6) chol_factor: blocked right-looking, panel=8 cols in warp 0,
//    parallel trailing update; 16 CTA barriers total (was 128)
// ============================================================
__global__ __launch_bounds__(256) void chol_factor(void) {
    __shared__ float sM[DSUB * 65];
    __shared__ float sD[DSUB];
    const int k = blockIdx.x, tid = threadIdx.x;
    const int lane = tid & 31;
    const int warp = tid >> 5;

    for (int idx = tid; idx < DSUB * DSUB; idx += 256) {
        float s = 0.f;
        #pragma unroll 8
        for (int b = 0; b < 32; b++) s += g_Gpart[k][b][idx];
        int i = idx >> 6, j = idx & 63;
        sM[i * 65 + j] = (i == j ? 1.f : 0.f) + COEFF * s;
    }
    __syncthreads();

    const int ui = tid >> 2;          // trailing-update row 0..63
    const int ub = tid & 3;           // trailing-update col base
    for (int p0 = 0; p0 < DSUB; p0 += 8) {
        // ---- panel factor: columns p0..p0+7, warp 0 only ----
        if (warp == 0) {
            #pragma unroll
            for (int jj = 0; jj < 8; jj++) {
                const int j = p0 + jj;
                float d = sM[j * 65 + j];
                float dinv = rsqrtf(d);
                if (lane == 0) sD[j] = d;
                #pragma unroll
                for (int h = 0; h < 2; h++) {
                    int i = lane + h * 32;
                    if (i > j) sM[i * 65 + j] *= dinv;
                }
                __syncwarp();
                for (int p = j + 1; p < p0 + 8; p++) {
                    float cp = sM[p * 65 + j];
                    #pragma unroll
                    for (int h = 0; h < 2; h++) {
                        int i = lane + h * 32;
                        if (i >= p) sM[i * 65 + p] -= sM[i * 65 + j] * cp;
                    }
                    __syncwarp();
                }
                if (lane == 0) sM[j * 65 + j] = dinv;   // diag := 1/sqrt for solver
                __syncwarp();
            }
        }
        __syncthreads();
        // ---- trailing update: A[p1.., p1..] -= Lpanel Lpanel^T ----
        const int p1 = p0 + 8;
        if (p1 < DSUB && ui >= p1) {
            float lrow[8];
            #pragma unroll
            for (int jj = 0; jj < 8; jj++) lrow[jj] = sM[ui * 65 + p0 + jj];
            #pragma unroll
            for (int qq = 0; qq < 16; qq++) {
                int c = ub + (qq << 2);
                if (c >= p1 && c <= ui) {
                    float s = 0.f;
                    #pragma unroll
                    for (int jj = 0; jj < 8; jj++)
                        s += lrow[jj] * sM[c * 65 + p0 + jj];
                    sM[ui * 65 + c] -= s;
                }
            }
        }
        __syncthreads();
    }

    if (tid == 0) {
        float r = 0.f;
        #pragma unroll 4
        for (int j = 0; j < DSUB; j++) r += logf(sD[j]);
        g_R[k] = 0.5f * r;
    }
    __syncthreads();
    for (int idx = tid; idx < DSUB * 65; idx += 256) g_Lf[k][idx] = sM[idx];
}

// ============================================================
// 7) finalize softmax weights + output tail
// ============================================================
__global__ void finalize_w(const float* __restrict__ taup, float* __restrict__ out_tail) {
    if (threadIdx.x != 0) return;
    float R0 = g_R[0], R1 = g_R[1], R2 = g_R[2];
    float d0 = R0, d1 = R1 - R0, d2 = R2 - R1;
    float mean = (d0 + d1 + d2) * (1.f / 3.f);
    float e0 = d0 - mean, e1 = d1 - mean, e2 = d2 - mean;
    float sd = sqrtf((e0 * e0 + e1 * e1 + e2 * e2) * 0.5f);   // ddof=1
    float s = 1.f / (sd + 1e-6f);
    float n0 = e0 * s, n1 = e1 * s, n2 = e2 * s;
    float tau = taup[0];
    float a0 = n0 / tau, a1 = n1 / tau, a2 = n2 / tau;
    float mx = fmaxf(a0, fmaxf(a1, a2));
    float x0 = expf(a0 - mx), x1 = expf(a1 - mx), x2 = expf(a2 - mx);
    float isum = 1.f / (x0 + x1 + x2);
    float w0 = x0 * isum, w1 = x1 * isum, w2 = x2 * isum;
    out_tail[0] = w0; out_tail[1] = w1; out_tail[2] = w2;
    out_tail[3] = n0; out_tail[4] = n1; out_tail[5] = n2;
    out_tail[6] = d0; out_tail[7] = d1; out_tail[8] = d2;
    g_s[0] = ETA_C * COEFF * w0;
    g_s[1] = ETA_C * COEFF * w1;
    g_s[2] = ETA_C * COEFF * w2;
}

// ============================================================
// 8) trisolve: Bs[k] = s_k * M^{-1} (sum WWop)   (128 RHS)
// ============================================================
#define TRI_SMEM ((DSUB * 65 + DSUB * 132) * 4)
__global__ __launch_bounds__(128) void trisolve_B(void) {
    extern __shared__ float tsm[];
    float* sL = tsm;                  // [64][65], diag = 1/sqrt
    float* sY = tsm + DSUB * 65;      // [64][132]
    const int k = blockIdx.x, c = threadIdx.x;

    for (int idx = c; idx < DSUB * 65; idx += 128) sL[idx] = g_Lf[k][idx];
    __syncthreads();

    const float sk = g_s[k];
    for (int i = 0; i < DSUB; i++) {
        float s = g_WWop[k][0][i][c] + g_WWop[k][1][i][c]
                + g_WWop[k][2][i][c] + g_WWop[k][3][i][c];
        float s0 = 0.f, s1 = 0.f, s2 = 0.f, s3 = 0.f;
        int j = 0;
        for (; j + 4 <= i; j += 4) {
            s0 += sL[i * 65 + j + 0] * sY[(j + 0) * 132 + c];
            s1 += sL[i * 65 + j + 1] * sY[(j + 1) * 132 + c];
            s2 += sL[i * 65 + j + 2] * sY[(j + 2) * 132 + c];
            s3 += sL[i * 65 + j + 3] * sY[(j + 3) * 132 + c];
        }
        for (; j < i; j++) s0 += sL[i * 65 + j] * sY[j * 132 + c];
        sY[i * 132 + c] = (s - ((s0 + s1) + (s2 + s3))) * sL[i * 65 + i];
    }
    for (int i = DSUB - 1; i >= 0; i--) {
        float s = sY[i * 132 + c];
        float s0 = 0.f, s1 = 0.f, s2 = 0.f, s3 = 0.f;
        int j = i + 1;
        for (; j + 4 <= DSUB; j += 4) {
            s0 += sL[(j + 0) * 65 + i] * sY[(j + 0) * 132 + c];
            s1 += sL[(j + 1) * 65 + i] * sY[(j + 1) * 132 + c];
            s2 += sL[(j + 2) * 65 + i] * sY[(j + 2) * 132 + c];
            s3 += sL[(j + 3) * 65 + i] * sY[(j + 3) * 132 + c];
        }
        for (; j < DSUB; j++) s0 += sL[j * 65 + i] * sY[j * 132 + c];
        float x = (s - ((s0 + s1) + (s2 + s3))) * sL[i * 65 + i];
        sY[i * 132 + c] = x;
        g_Bs[k][i][c] = sk * x;
    }
}

// ============================================================
// 9) H_pre = HW + sum_k Z_k @ Bs_k - 0.15*(LHWp0+LHWp1) ; soft-thr ; LN
// ============================================================
__global__ __launch_bounds__(256) void fuse_out(const float* __restrict__ thrP,
                                                const float* __restrict__ gamP,
                                                const float* __restrict__ betP,
                                                float* __restrict__ out) {
    __shared__ float sAt[16][68];   // Z chunk transposed [d][row]
    __shared__ float sB[16][132];   // Bs chunk [d][col]
    const int tid = threadIdx.x;
    const int tx = tid & 15, ty = tid >> 4;
    const int r0 = blockIdx.x * 64;
    float acc[4][8] = {};

    for (int k = 0; k < KHOP; k++) {
        for (int d0 = 0; d0 < DSUB; d0 += 16) {
            int ar = tid >> 2, ac = (tid & 3) * 4;
            float4 a = *(const float4*)&g_Z[k][r0 + ar][d0 + ac];
            sAt[ac + 0][ar] = a.x; sAt[ac + 1][ar] = a.y;
            sAt[ac + 2][ar] = a.z; sAt[ac + 3][ar] = a.w;
            int dl = tid >> 4, c8 = (tid & 15) * 8;
            float4 b1 = *(const float4*)&g_Bs[k][d0 + dl][c8];
            float4 b2 = *(const float4*)&g_Bs[k][d0 + dl][c8 + 4];
            *(float4*)&sB[dl][c8]     = b1;
            *(float4*)&sB[dl][c8 + 4] = b2;
            __syncthreads();
            #pragma unroll
            for (int kk = 0; kk < 16; kk++) {
                float ra[4], rb[8];
                *(float4*)&ra[0] = *(const float4*)&sAt[kk][ty * 4];
                *(float4*)&rb[0] = *(const float4*)&sB[kk][tx * 8];
                *(float4*)&rb[4] = *(const float4*)&sB[kk][tx * 8 + 4];
                #pragma unroll
                for (int i = 0; i < 4; i++)
                    #pragma unroll
                    for (int j = 0; j < 8; j++) acc[i][j] += ra[i] * rb[j];
            }
            __syncthreads();
        }
    }

    float thr_[8], gam_[8], bet_[8];
    #pragma unroll
    for (int j = 0; j < 8; j++) {
        int c = tx * 8 + j;
        thr_[j] = fabsf(__ldg(&thrP[c]));
        gam_[j] = __ldg(&gamP[c]);
        bet_[j] = __ldg(&betP[c]);
    }
    #pragma unroll
    for (int i = 0; i < 4; i++) {
        size_t row = r0 + ty * 4 + i;
        float4 hw1 = *(const float4*)&g_HW[row * ODIM + tx * 8];
        float4 hw2 = *(const float4*)&g_HW[row * ODIM + tx * 8 + 4];
        float4 p1a = *(const float4*)&g_LHWp[0][row * ODIM + tx * 8];
        float4 p1b = *(const float4*)&g_LHWp[0][row * ODIM + tx * 8 + 4];
        float4 p2a = *(const float4*)&g_LHWp[1][row * ODIM + tx * 8];
        float4 p2b = *(const float4*)&g_LHWp[1][row * ODIM + tx * 8 + 4];
        float bias[8] = {hw1.x - LAPSC * (p1a.x + p2a.x), hw1.y - LAPSC * (p1a.y + p2a.y),
                         hw1.z - LAPSC * (p1a.z + p2a.z), hw1.w - LAPSC * (p1a.w + p2a.w),
                         hw2.x - LAPSC * (p1b.x + p2b.x), hw2.y - LAPSC * (p1b.y + p2b.y),
                         hw2.z - LAPSC * (p1b.z + p2b.z), hw2.w - LAPSC * (p1b.w + p2b.w)};
        float v[8], s = 0.f, q = 0.f;
        #pragma unroll
        for (int j = 0; j < 8; j++) {
            float p = acc[i][j] + bias[j];
            float ap = fabsf(p) - thr_[j];
            float val = ap > 0.f ? copysignf(ap, p) : 0.f;
            v[j] = val; s += val; q += val * val;
        }
        #pragma unroll
        for (int o = 8; o >= 1; o >>= 1) {
            s += __shfl_xor_sync(0xffffffffu, s, o);
            q += __shfl_xor_sync(0xffffffffu, q, o);
        }
        float mu = s * (1.f / 128.f);
        float var = q * (1.f / 128.f) - mu * mu;
        float rs = rsqrtf(var + LN_EPSF);
        float o_[8];
        #pragma unroll
        for (int j = 0; j < 8; j++) o_[j] = (v[j] - mu) * rs * gam_[j] + bet_[j];
        *(float4*)&out[row * ODIM + tx * 8]     = make_float4(o_[0], o_[1], o_[2], o_[3]);
        *(float4*)&out[row * ODIM + tx * 8 + 4] = make_float4(o_[4], o_[5], o_[6], o_[7]);
    }
}

// ============================================================
extern "C" void kernel_launch(void* const* d_in, const int* in_sizes, int n_in,
                              void* d_out, int out_size) {
    const float* H    = (const float*)d_in[0];
    const float* hop  = (const float*)d_in[1];
    const float* L    = (const float*)d_in[2];
    const float* Wst  = (const float*)d_in[3];
    const float* Wout = (const float*)d_in[4];
    const float* thr  = (const float*)d_in[5];
    const float* gam  = (const float*)d_in[6];
    const float* bet  = (const float*)d_in[7];
    const float* tau  = (const float*)d_in[8];
    float* out = (float*)d_out;
    float* out_tail = out + (size_t)NN * ODIM;

    float* d_HW;
    cudaGetSymbolAddress((void**)&d_HW, g_HW);
    float* d_LHWp;
    cudaGetSymbolAddress((void**)&d_LHWp, g_LHWp);

    const int zsmem = 2 * 64 * 257 * 4;                           // 131584
    cudaFuncSetAttribute(compute_Z,  cudaFuncAttributeMaxDynamicSharedMemorySize, zsmem);
    cudaFuncSetAttribute(trisolve_B, cudaFuncAttributeMaxDynamicSharedMemorySize, TRI_SMEM);
    cudaFuncSetAttribute(gemmLHW,    cudaFuncAttributeMaxDynamicSharedMemorySize, G2_SMEM);

    // ---- fork: spine B (Z/G/WWo/chol/finalize/trisolve) on side stream ----
    cudaEventRecord(g_sr.evFork, 0);
    cudaStreamWaitEvent(g_sr.s2, g_sr.evFork, 0);

    compute_Z<<<dim3(128, KHOP), 256, zsmem, g_sr.s2>>>(hop, Wst);
    compute_G<<<dim3(32, KHOP), 256, 0, g_sr.s2>>>();
    computeWWo<<<dim3(KHOP, 4), 256, 0, g_sr.s2>>>(Wst, Wout);
    chol_factor<<<KHOP, 256, 0, g_sr.s2>>>();
    finalize_w<<<1, 32, 0, g_sr.s2>>>(tau, out_tail);
    trisolve_B<<<KHOP, 128, TRI_SMEM, g_sr.s2>>>();
    cudaEventRecord(g_sr.evJoin, g_sr.s2);

    // ---- spine A (HW -> big gemm) on main stream ----
    computeHW<<<128, 256>>>(H, Wout);
    gemmLHW<<<dim3(2, 128), 256, G2_SMEM>>>(L, d_HW, d_LHWp);

    // ---- join, then fused epilogue ----
    cudaStreamWaitEvent(0, g_sr.evJoin, 0);
    fuse_out<<<128, 256>>>(thr, gam, bet, out);
}

// round 11
// speedup vs baseline: 1.5517x; 1.5517x over previous
#include <cuda_runtime.h>
#include <cstdint>
#include <math.h>

// ---------------- problem constants ----------------
#define NN      8192
#define FDIM    256
#define DSUB    64
#define KHOP    3
#define ODIM    128
#define COEFF   0.03125f           // d/(n*eps^2) = 64/(8192*0.25)
#define ETA_C   0.5f
#define LAPSC   0.15f              // ETA*LAMBDA_LAP
#define LN_EPSF 1e-5f

// ---------------- device scratch (no allocs allowed) ----------------
__device__ float g_Z[KHOP][NN][DSUB];           // 6.3 MB
__device__ float g_Gpart[KHOP][32][DSUB*DSUB];  // 1.6 MB
__device__ float g_G[KHOP][DSUB*DSUB];          // reduced Gram
__device__ float g_R[KHOP];
__device__ float g_s[KHOP];                     // ETA*coeff*w[k]
__device__ float g_Lf[KHOP][DSUB*65];           // Chol factor, diag = 1/sqrt
__device__ float g_WWop[KHOP][4][DSUB][ODIM];   // partial W[k] @ Wout^T
__device__ float g_Bs[KHOP][DSUB][ODIM];        // s_k * M^{-1} WWo
__device__ float g_HW[NN*ODIM];                 // H @ Wout^T   (4 MB)
__device__ float g_LHWp[2][NN*ODIM];            // split-K partials of L @ HW (8 MB)

// ---------------- streams/events created at load time ----------------
struct StreamRes {
    cudaStream_t s2;
    cudaEvent_t evFork, evJoin;
    StreamRes() {
        cudaStreamCreateWithFlags(&s2, cudaStreamNonBlocking);
        cudaEventCreateWithFlags(&evFork, cudaEventDisableTiming);
        cudaEventCreateWithFlags(&evJoin, cudaEventDisableTiming);
    }
};
static StreamRes g_sr;

// ============================================================
// 1) HW = H @ Wout^T  [8192 x 128, K=256]
// ============================================================
__global__ __launch_bounds__(256) void computeHW(const float* __restrict__ H,
                                                 const float* __restrict__ Wout) {
    __shared__ float sAt[16][68];
    __shared__ float sB[16][132];
    const int tid = threadIdx.x;
    const int tx = tid & 15, ty = tid >> 4;
    const int r0 = blockIdx.x * 64;
    float acc[4][8] = {};

    for (int f0 = 0; f0 < FDIM; f0 += 16) {
        int ar = tid >> 2, ac = (tid & 3) * 4;
        float4 a = *(const float4*)&H[(size_t)(r0 + ar) * FDIM + f0 + ac];
        sAt[ac + 0][ar] = a.x; sAt[ac + 1][ar] = a.y;
        sAt[ac + 2][ar] = a.z; sAt[ac + 3][ar] = a.w;
        int bo = tid >> 1, bf = (tid & 1) * 8;
        const float* wpp = Wout + (size_t)bo * FDIM + f0 + bf;
        float4 b1 = *(const float4*)wpp;
        float4 b2 = *(const float4*)(wpp + 4);
        sB[bf + 0][bo] = b1.x; sB[bf + 1][bo] = b1.y;
        sB[bf + 2][bo] = b1.z; sB[bf + 3][bo] = b1.w;
        sB[bf + 4][bo] = b2.x; sB[bf + 5][bo] = b2.y;
        sB[bf + 6][bo] = b2.z; sB[bf + 7][bo] = b2.w;
        __syncthreads();
        #pragma unroll
        for (int kk = 0; kk < 16; kk++) {
            float ra[4], rb[8];
            *(float4*)&ra[0] = *(const float4*)&sAt[kk][ty * 4];
            *(float4*)&rb[0] = *(const float4*)&sB[kk][tx * 8];
            *(float4*)&rb[4] = *(const float4*)&sB[kk][tx * 8 + 4];
            #pragma unroll
            for (int i = 0; i < 4; i++)
                #pragma unroll
                for (int j = 0; j < 8; j++) acc[i][j] += ra[i] * rb[j];
        }
        __syncthreads();
    }
    #pragma unroll
    for (int i = 0; i < 4; i++) {
        size_t row = r0 + ty * 4 + i;
        *(float4*)&g_HW[row * ODIM + tx * 8]     = make_float4(acc[i][0], acc[i][1], acc[i][2], acc[i][3]);
        *(float4*)&g_HW[row * ODIM + tx * 8 + 4] = make_float4(acc[i][4], acc[i][5], acc[i][6], acc[i][7]);
    }
}

// ============================================================
// 2) Z[k] = hop_feats[k] @ W[k]^T
// ============================================================
__global__ __launch_bounds__(256) void compute_Z(const float* __restrict__ hop,
                                                 const float* __restrict__ Wst) {
    extern __shared__ float sm[];
    float* sH = sm;               // [64][257]
    float* sW = sm + 64 * 257;    // [64][257]
    const int tid = threadIdx.x;
    const int k = blockIdx.y;
    const int r0 = blockIdx.x * 64;

    const float* hp = hop + ((size_t)k * NN + r0) * FDIM;
    const float* wp = Wst + (size_t)k * DSUB * FDIM;
    for (int idx = tid * 4; idx < 64 * FDIM; idx += 1024) {
        int r = idx >> 8, c = idx & 255;
        float4 v = *(const float4*)(hp + idx);
        sH[r * 257 + c + 0] = v.x; sH[r * 257 + c + 1] = v.y;
        sH[r * 257 + c + 2] = v.z; sH[r * 257 + c + 3] = v.w;
        float4 w = *(const float4*)(wp + idx);
        sW[r * 257 + c + 0] = w.x; sW[r * 257 + c + 1] = w.y;
        sW[r * 257 + c + 2] = w.z; sW[r * 257 + c + 3] = w.w;
    }
    __syncthreads();

    const int tx = tid & 15, ty = tid >> 4;
    float acc[4][4] = {};
    #pragma unroll 4
    for (int f = 0; f < FDIM; f++) {
        float a[4], b[4];
        #pragma unroll
        for (int i = 0; i < 4; i++) a[i] = sH[(ty * 4 + i) * 257 + f];
        #pragma unroll
        for (int j = 0; j < 4; j++) b[j] = sW[(tx * 4 + j) * 257 + f];
        #pragma unroll
        for (int i = 0; i < 4; i++)
            #pragma unroll
            for (int j = 0; j < 4; j++) acc[i][j] += a[i] * b[j];
    }
    #pragma unroll
    for (int i = 0; i < 4; i++) {
        float4 o = make_float4(acc[i][0], acc[i][1], acc[i][2], acc[i][3]);
        *(float4*)&g_Z[k][r0 + ty * 4 + i][tx * 4] = o;
    }
}

// ============================================================
// 3) partial Gram: each block (32 per k) does 256 rows of Z^T Z
// ============================================================
__global__ __launch_bounds__(256) void compute_G(void) {
    __shared__ float sZ[16 * DSUB];
    const int tid = threadIdx.x;
    const int k = blockIdx.y;
    const int r0 = blockIdx.x * 256;
    const int tx = tid & 15, ty = tid >> 4;
    float acc[4][4] = {};

    for (int chunk = 0; chunk < 256; chunk += 16) {
        int lr = tid >> 4, lc = (tid & 15) * 4;
        *(float4*)&sZ[lr * DSUB + lc] = *(const float4*)&g_Z[k][r0 + chunk + lr][lc];
        __syncthreads();
        #pragma unroll
        for (int rr = 0; rr < 16; rr++) {
            float4 a = *(const float4*)&sZ[rr * DSUB + ty * 4];
            float4 b = *(const float4*)&sZ[rr * DSUB + tx * 4];
            float av[4] = {a.x, a.y, a.z, a.w};
            float bv[4] = {b.x, b.y, b.z, b.w};
            #pragma unroll
            for (int i = 0; i < 4; i++)
                #pragma unroll
                for (int j = 0; j < 4; j++) acc[i][j] += av[i] * bv[j];
        }
        __syncthreads();
    }
    #pragma unroll
    for (int i = 0; i < 4; i++)
        #pragma unroll
        for (int j = 0; j < 4; j++)
            g_Gpart[k][blockIdx.x][(ty * 4 + i) * DSUB + tx * 4 + j] = acc[i][j];
}

// ============================================================
// 3b) reduce_G: grid (KHOP, 16) x 256 thr; one element per thread
// ============================================================
__global__ __launch_bounds__(256) void reduce_G(void) {
    const int k = blockIdx.x;
    const int idx = blockIdx.y * 256 + threadIdx.x;   // 0..4095
    float s = 0.f;
    #pragma unroll
    for (int b = 0; b < 32; b++) s += g_Gpart[k][b][idx];
    int i = idx >> 6, j = idx & 63;
    g_G[k][idx] = (i == j ? 1.f : 0.f) + COEFF * s;   // M = I + coeff*G
}

// ============================================================
// 4) LHWp[kh] = L[:, kh-half] @ HW[kh-half, :] ; tf32 mma + cp.async
// ============================================================
#define APAD 36
#define BPAD 136
#define ASTG (64 * APAD)               // 2304 floats (9216 B)
#define BSTG (32 * BPAD)               // 4352 floats (17408 B)
#define STGF (ASTG + BSTG)             // 6656 floats (26624 B)
#define NSTAGE 4
#define G2_SMEM (NSTAGE * STGF * 4)    // 106496 B
#define KHALF (NN / 2)                 // 4096

__device__ __forceinline__ void mma_tf32_16x8x8(float* c, const uint32_t* a,
                                                const uint32_t* b) {
    asm volatile(
        "mma.sync.aligned.m16n8k8.row.col.f32.tf32.tf32.f32 "
        "{%0,%1,%2,%3}, {%4,%5,%6,%7}, {%8,%9}, {%0,%1,%2,%3};"
        : "+f"(c[0]), "+f"(c[1]), "+f"(c[2]), "+f"(c[3])
        : "r"(a[0]), "r"(a[1]), "r"(a[2]), "r"(a[3]), "r"(b[0]), "r"(b[1]));
}

__global__ __launch_bounds__(256, 2) void gemmLHW(const float* __restrict__ L,
                                                  const float* __restrict__ HW,
                                                  float* __restrict__ LHWp) {
    extern __shared__ float smx[];
    uint32_t sb;
    asm("{ .reg .u64 t; cvta.to.shared.u64 t, %1; cvt.u32.u64 %0, t; }"
        : "=r"(sb) : "l"(smx));

    const int tid = threadIdx.x;
    const int lane = tid & 31;
    const int warp = tid >> 5;
    const int g = lane >> 2, t = lane & 3;
    const int wm = (warp & 1) * 32;
    const int wn = (warp >> 1) * 32;
    const int m0 = blockIdx.y * 64;
    const int kh = blockIdx.x;                    // 0 or 1
    const size_t koff = (size_t)kh * KHALF;

    const int ar0 = tid >> 3, ac0 = (tid & 7) * 4;   // A rows ar0, ar0+32
    const int br0 = tid >> 5, bc0 = (tid & 31) * 4;  // B rows br0+8q

    auto issue = [&](int stg) {
        const uint32_t st = sb + (uint32_t)(stg & (NSTAGE - 1)) * (STGF * 4);
        const float* As = L + (size_t)(m0 + ar0) * NN + koff + (size_t)stg * 32 + ac0;
        #pragma unroll
        for (int q = 0; q < 2; q++) {
            uint32_t d = st + (uint32_t)((ar0 + q * 32) * APAD + ac0) * 4u;
            asm volatile("cp.async.cg.shared.global [%0], [%1], 16;"
                         :: "r"(d), "l"(As + (size_t)q * 32 * NN) : "memory");
        }
        const float* Bs = HW + (koff + (size_t)stg * 32 + br0) * ODIM + bc0;
        const uint32_t bb = st + ASTG * 4u;
        #pragma unroll
        for (int q = 0; q < 4; q++) {
            uint32_t d = bb + (uint32_t)((br0 + q * 8) * BPAD + bc0) * 4u;
            asm volatile("cp.async.cg.shared.global [%0], [%1], 16;"
                         :: "r"(d), "l"(Bs + (size_t)q * 8 * ODIM) : "memory");
        }
    };

    #pragma unroll
    for (int s = 0; s < NSTAGE - 1; s++) {
        issue(s);
        asm volatile("cp.async.commit_group;" ::: "memory");
    }

    float acc[2][4][4] = {};
    const int NITER = KHALF / 32;   // 128

    for (int it = 0; it < NITER; it++) {
        asm volatile("cp.async.wait_group %0;" :: "n"(NSTAGE - 2) : "memory");
        __syncthreads();
        int nx = it + NSTAGE - 1;
        if (nx < NITER) issue(nx);
        asm volatile("cp.async.commit_group;" ::: "memory");

        const float* pa = smx + (it & (NSTAGE - 1)) * STGF;
        const float* pb = pa + ASTG;
        const uint32_t* ua = (const uint32_t*)pa;
        const uint32_t* ub = (const uint32_t*)pb;
        #pragma unroll
        for (int ks = 0; ks < 4; ks++) {
            const int kk = ks * 8 + t;
            uint32_t af[2][4], bf[4][2];
            #pragma unroll
            for (int mt = 0; mt < 2; mt++) {
                const int r = wm + mt * 16 + g;
                af[mt][0] = ua[r * APAD + kk];
                af[mt][1] = ua[(r + 8) * APAD + kk];
                af[mt][2] = ua[r * APAD + kk + 4];
                af[mt][3] = ua[(r + 8) * APAD + kk + 4];
            }
            #pragma unroll
            for (int nt = 0; nt < 4; nt++) {
                const int n = wn + nt * 8 + g;
                bf[nt][0] = ub[kk * BPAD + n];
                bf[nt][1] = ub[(kk + 4) * BPAD + n];
            }
            #pragma unroll
            for (int mt = 0; mt < 2; mt++)
                #pragma unroll
                for (int nt = 0; nt < 4; nt++)
                    mma_tf32_16x8x8(acc[mt][nt], af[mt], bf[nt]);
        }
    }

    float* outp = LHWp + (size_t)kh * NN * ODIM;
    const int er = g, ec = t * 2;
    #pragma unroll
    for (int mt = 0; mt < 2; mt++) {
        #pragma unroll
        for (int nt = 0; nt < 4; nt++) {
            const int row = m0 + wm + mt * 16 + er;
            const int col = wn + nt * 8 + ec;
            *(float2*)&outp[(size_t)row * ODIM + col] =
                make_float2(acc[mt][nt][0], acc[mt][nt][1]);
            *(float2*)&outp[(size_t)(row + 8) * ODIM + col] =
                make_float2(acc[mt][nt][2], acc[mt][nt][3]);
        }
    }
}

// ============================================================
// 5) WWo partials: grid (KHOP, 4); each CTA does 64 f-values
// ============================================================
__global__ __launch_bounds__(256) void computeWWo(const float* __restrict__ Wst,
                                                  const float* __restrict__ Wout) {
    __shared__ float sAt[16][68];
    __shared__ float sB[16][132];
    const int tid = threadIdx.x;
    const int tx = tid & 15, ty = tid >> 4;
    const int k = blockIdx.x;
    const int fbase = blockIdx.y * 64;
    float acc[4][8] = {};

    for (int fo = 0; fo < 64; fo += 16) {
        int f0 = fbase + fo;
        int ar = tid >> 2, ac = (tid & 3) * 4;
        float4 a = *(const float4*)&Wst[((size_t)k * DSUB + ar) * FDIM + f0 + ac];
        sAt[ac + 0][ar] = a.x; sAt[ac + 1][ar] = a.y;
        sAt[ac + 2][ar] = a.z; sAt[ac + 3][ar] = a.w;
        int bo = tid >> 1, bf = (tid & 1) * 8;
        const float* wpp = Wout + (size_t)bo * FDIM + f0 + bf;
        float4 b1 = *(const float4*)wpp;
        float4 b2 = *(const float4*)(wpp + 4);
        sB[bf + 0][bo] = b1.x; sB[bf + 1][bo] = b1.y;
        sB[bf + 2][bo] = b1.z; sB[bf + 3][bo] = b1.w;
        sB[bf + 4][bo] = b2.x; sB[bf + 5][bo] = b2.y;
        sB[bf + 6][bo] = b2.z; sB[bf + 7][bo] = b2.w;
        __syncthreads();
        #pragma unroll
        for (int kk = 0; kk < 16; kk++) {
            float ra[4], rb[8];
            *(float4*)&ra[0] = *(const float4*)&sAt[kk][ty * 4];
            *(float4*)&rb[0] = *(const float4*)&sB[kk][tx * 8];
            *(float4*)&rb[4] = *(const float4*)&sB[kk][tx * 8 + 4];
            #pragma unroll
            for (int i = 0; i < 4; i++)
                #pragma unroll
                for (int j = 0; j < 8; j++) acc[i][j] += ra[i] * rb[j];
        }
        __syncthreads();
    }
    #pragma unroll
    for (int i = 0; i < 4; i++) {
        int d = ty * 4 + i;
        *(float4*)&g_WWop[k][blockIdx.y][d][tx * 8]     = make_float4(acc[i][0], acc[i][1], acc[i][2], acc[i][3]);
        *(float4*)&g_WWop[k][blockIdx.y][d][tx * 8 + 4] = make_float4(acc[i][4], acc[i][5], acc[i][6], acc[i][7]);
    }
}

// ============================================================
// 6) chol_factor: loads pre-reduced M, blocked right-looking factor
// ============================================================
__global__ __launch_bounds__(256) void chol_factor(void) {
    __shared__ float sM[DSUB * 65];
    __shared__ float sD[DSUB];
    const int k = blockIdx.x, tid = threadIdx.x;
    const int lane = tid & 31;
    const int warp = tid >> 5;

    for (int idx = tid; idx < DSUB * DSUB; idx += 256) {
        int i = idx >> 6, j = idx & 63;
        sM[i * 65 + j] = g_G[k][idx];
    }
    __syncthreads();

    const int ui = tid >> 2;          // trailing-update row 0..63
    const int ub = tid & 3;           // trailing-update col base
    for (int p0 = 0; p0 < DSUB; p0 += 8) {
        // ---- panel factor: columns p0..p0+7, warp 0 only ----
        if (warp == 0) {
            #pragma unroll
            for (int jj = 0; jj < 8; jj++) {
                const int j = p0 + jj;
                float d = sM[j * 65 + j];
                float dinv = rsqrtf(d);
                if (lane == 0) sD[j] = d;
                #pragma unroll
                for (int h = 0; h < 2; h++) {
                    int i = lane + h * 32;
                    if (i > j) sM[i * 65 + j] *= dinv;
                }
                __syncwarp();
                for (int p = j + 1; p < p0 + 8; p++) {
                    float cp = sM[p * 65 + j];
                    #pragma unroll
                    for (int h = 0; h < 2; h++) {
                        int i = lane + h * 32;
                        if (i >= p) sM[i * 65 + p] -= sM[i * 65 + j] * cp;
                    }
                    __syncwarp();
                }
                if (lane == 0) sM[j * 65 + j] = dinv;   // diag := 1/sqrt for solver
                __syncwarp();
            }
        }
        __syncthreads();
        // ---- trailing update: A[p1.., p1..] -= Lpanel Lpanel^T ----
        const int p1 = p0 + 8;
        if (p1 < DSUB && ui >= p1) {
            float lrow[8];
            #pragma unroll
            for (int jj = 0; jj < 8; jj++) lrow[jj] = sM[ui * 65 + p0 + jj];
            #pragma unroll
            for (int qq = 0; qq < 16; qq++) {
                int c = ub + (qq << 2);
                if (c >= p1 && c <= ui) {
                    float s = 0.f;
                    #pragma unroll
                    for (int jj = 0; jj < 8; jj++)
                        s += lrow[jj] * sM[c * 65 + p0 + jj];
                    sM[ui * 65 + c] -= s;
                }
            }
        }
        __syncthreads();
    }

    if (tid == 0) {
        float r = 0.f;
        #pragma unroll 4
        for (int j = 0; j < DSUB; j++) r += logf(sD[j]);
        g_R[k] = 0.5f * r;
    }
    __syncthreads();
    for (int idx = tid; idx < DSUB * 65; idx += 256) g_Lf[k][idx] = sM[idx];
}

// ============================================================
// 7) finalize softmax weights + output tail
// ============================================================
__global__ void finalize_w(const float* __restrict__ taup, float* __restrict__ out_tail) {
    if (threadIdx.x != 0) return;
    float R0 = g_R[0], R1 = g_R[1], R2 = g_R[2];
    float d0 = R0, d1 = R1 - R0, d2 = R2 - R1;
    float mean = (d0 + d1 + d2) * (1.f / 3.f);
    float e0 = d0 - mean, e1 = d1 - mean, e2 = d2 - mean;
    float sd = sqrtf((e0 * e0 + e1 * e1 + e2 * e2) * 0.5f);   // ddof=1
    float s = 1.f / (sd + 1e-6f);
    float n0 = e0 * s, n1 = e1 * s, n2 = e2 * s;
    float tau = taup[0];
    float a0 = n0 / tau, a1 = n1 / tau, a2 = n2 / tau;
    float mx = fmaxf(a0, fmaxf(a1, a2));
    float x0 = expf(a0 - mx), x1 = expf(a1 - mx), x2 = expf(a2 - mx);
    float isum = 1.f / (x0 + x1 + x2);
    float w0 = x0 * isum, w1 = x1 * isum, w2 = x2 * isum;
    out_tail[0] = w0; out_tail[1] = w1; out_tail[2] = w2;
    out_tail[3] = n0; out_tail[4] = n1; out_tail[5] = n2;
    out_tail[6] = d0; out_tail[7] = d1; out_tail[8] = d2;
    g_s[0] = ETA_C * COEFF * w0;
    g_s[1] = ETA_C * COEFF * w1;
    g_s[2] = ETA_C * COEFF * w2;
}

// ============================================================
// 8) trisolve: Bs[k] = s_k * M^{-1} (sum WWop)   (128 RHS)
// ============================================================
#define TRI_SMEM ((DSUB * 65 + DSUB * 132) * 4)
__global__ __launch_bounds__(128) void trisolve_B(void) {
    extern __shared__ float tsm[];
    float* sL = tsm;                  // [64][65], diag = 1/sqrt
    float* sY = tsm + DSUB * 65;      // [64][132]
    const int k = blockIdx.x, c = threadIdx.x;

    for (int idx = c; idx < DSUB * 65; idx += 128) sL[idx] = g_Lf[k][idx];
    __syncthreads();

    const float sk = g_s[k];
    for (int i = 0; i < DSUB; i++) {
        float s = g_WWop[k][0][i][c] + g_WWop[k][1][i][c]
                + g_WWop[k][2][i][c] + g_WWop[k][3][i][c];
        float s0 = 0.f, s1 = 0.f, s2 = 0.f, s3 = 0.f;
        int j = 0;
        for (; j + 4 <= i; j += 4) {
            s0 += sL[i * 65 + j + 0] * sY[(j + 0) * 132 + c];
            s1 += sL[i * 65 + j + 1] * sY[(j + 1) * 132 + c];
            s2 += sL[i * 65 + j + 2] * sY[(j + 2) * 132 + c];
            s3 += sL[i * 65 + j + 3] * sY[(j + 3) * 132 + c];
        }
        for (; j < i; j++) s0 += sL[i * 65 + j] * sY[j * 132 + c];
        sY[i * 132 + c] = (s - ((s0 + s1) + (s2 + s3))) * sL[i * 65 + i];
    }
    for (int i = DSUB - 1; i >= 0; i--) {
        float s = sY[i * 132 + c];
        float s0 = 0.f, s1 = 0.f, s2 = 0.f, s3 = 0.f;
        int j = i + 1;
        for (; j + 4 <= DSUB; j += 4) {
            s0 += sL[(j + 0) * 65 + i] * sY[(j + 0) * 132 + c];
            s1 += sL[(j + 1) * 65 + i] * sY[(j + 1) * 132 + c];
            s2 += sL[(j + 2) * 65 + i] * sY[(j + 2) * 132 + c];
            s3 += sL[(j + 3) * 65 + i] * sY[(j + 3) * 132 + c];
        }
        for (; j < DSUB; j++) s0 += sL[j * 65 + i] * sY[j * 132 + c];
        float x = (s - ((s0 + s1) + (s2 + s3))) * sL[i * 65 + i];
        sY[i * 132 + c] = x;
        g_Bs[k][i][c] = sk * x;
    }
}

// ============================================================
// 9) H_pre = HW + sum_k Z_k @ Bs_k - 0.15*(LHWp0+LHWp1) ; soft-thr ; LN
// ============================================================
__global__ __launch_bounds__(256) void fuse_out(const float* __restrict__ thrP,
                                                const float* __restrict__ gamP,
                                                const float* __restrict__ betP,
                                                float* __restrict__ out) {
    __shared__ float sAt[16][68];   // Z chunk transposed [d][row]
    __shared__ float sB[16][132];   // Bs chunk [d][col]
    const int tid = threadIdx.x;
    const int tx = tid & 15, ty = tid >> 4;
    const int r0 = blockIdx.x * 64;
    float acc[4][8] = {};

    for (int k = 0; k < KHOP; k++) {
        for (int d0 = 0; d0 < DSUB; d0 += 16) {
            int ar = tid >> 2, ac = (tid & 3) * 4;
            float4 a = *(const float4*)&g_Z[k][r0 + ar][d0 + ac];
            sAt[ac + 0][ar] = a.x; sAt[ac + 1][ar] = a.y;
            sAt[ac + 2][ar] = a.z; sAt[ac + 3][ar] = a.w;
            int dl = tid >> 4, c8 = (tid & 15) * 8;
            float4 b1 = *(const float4*)&g_Bs[k][d0 + dl][c8];
            float4 b2 = *(const float4*)&g_Bs[k][d0 + dl][c8 + 4];
            *(float4*)&sB[dl][c8]     = b1;
            *(float4*)&sB[dl][c8 + 4] = b2;
            __syncthreads();
            #pragma unroll
            for (int kk = 0; kk < 16; kk++) {
                float ra[4], rb[8];
                *(float4*)&ra[0] = *(const float4*)&sAt[kk][ty * 4];
                *(float4*)&rb[0] = *(const float4*)&sB[kk][tx * 8];
                *(float4*)&rb[4] = *(const float4*)&sB[kk][tx * 8 + 4];
                #pragma unroll
                for (int i = 0; i < 4; i++)
                    #pragma unroll
                    for (int j = 0; j < 8; j++) acc[i][j] += ra[i] * rb[j];
            }
            __syncthreads();
        }
    }

    float thr_[8], gam_[8], bet_[8];
    #pragma unroll
    for (int j = 0; j < 8; j++) {
        int c = tx * 8 + j;
        thr_[j] = fabsf(__ldg(&thrP[c]));
        gam_[j] = __ldg(&gamP[c]);
        bet_[j] = __ldg(&betP[c]);
    }
    #pragma unroll
    for (int i = 0; i < 4; i++) {
        size_t row = r0 + ty * 4 + i;
        float4 hw1 = *(const float4*)&g_HW[row * ODIM + tx * 8];
        float4 hw2 = *(const float4*)&g_HW[row * ODIM + tx * 8 + 4];
        float4 p1a = *(const float4*)&g_LHWp[0][row * ODIM + tx * 8];
        float4 p1b = *(const float4*)&g_LHWp[0][row * ODIM + tx * 8 + 4];
        float4 p2a = *(const float4*)&g_LHWp[1][row * ODIM + tx * 8];
        float4 p2b = *(const float4*)&g_LHWp[1][row * ODIM + tx * 8 + 4];
        float bias[8] = {hw1.x - LAPSC * (p1a.x + p2a.x), hw1.y - LAPSC * (p1a.y + p2a.y),
                         hw1.z - LAPSC * (p1a.z + p2a.z), hw1.w - LAPSC * (p1a.w + p2a.w),
                         hw2.x - LAPSC * (p1b.x + p2b.x), hw2.y - LAPSC * (p1b.y + p2b.y),
                         hw2.z - LAPSC * (p1b.z + p2b.z), hw2.w - LAPSC * (p1b.w + p2b.w)};
        float v[8], s = 0.f, q = 0.f;
        #pragma unroll
        for (int j = 0; j < 8; j++) {
            float p = acc[i][j] + bias[j];
            float ap = fabsf(p) - thr_[j];
            float val = ap > 0.f ? copysignf(ap, p) : 0.f;
            v[j] = val; s += val; q += val * val;
        }
        #pragma unroll
        for (int o = 8; o >= 1; o >>= 1) {
            s += __shfl_xor_sync(0xffffffffu, s, o);
            q += __shfl_xor_sync(0xffffffffu, q, o);
        }
        float mu = s * (1.f / 128.f);
        float var = q * (1.f / 128.f) - mu * mu;
        float rs = rsqrtf(var + LN_EPSF);
        float o_[8];
        #pragma unroll
        for (int j = 0; j < 8; j++) o_[j] = (v[j] - mu) * rs * gam_[j] + bet_[j];
        *(float4*)&out[row * ODIM + tx * 8]     = make_float4(o_[0], o_[1], o_[2], o_[3]);
        *(float4*)&out[row * ODIM + tx * 8 + 4] = make_float4(o_[4], o_[5], o_[6], o_[7]);
    }
}

// ============================================================
extern "C" void kernel_launch(void* const* d_in, const int* in_sizes, int n_in,
                              void* d_out, int out_size) {
    const float* H    = (const float*)d_in[0];
    const float* hop  = (const float*)d_in[1];
    const float* L    = (const float*)d_in[2];
    const float* Wst  = (const float*)d_in[3];
    const float* Wout = (const float*)d_in[4];
    const float* thr  = (const float*)d_in[5];
    const float* gam  = (const float*)d_in[6];
    const float* bet  = (const float*)d_in[7];
    const float* tau  = (const float*)d_in[8];
    float* out = (float*)d_out;
    float* out_tail = out + (size_t)NN * ODIM;

    float* d_HW;
    cudaGetSymbolAddress((void**)&d_HW, g_HW);
    float* d_LHWp;
    cudaGetSymbolAddress((void**)&d_LHWp, g_LHWp);

    const int zsmem = 2 * 64 * 257 * 4;                           // 131584
    cudaFuncSetAttribute(compute_Z,  cudaFuncAttributeMaxDynamicSharedMemorySize, zsmem);
    cudaFuncSetAttribute(trisolve_B, cudaFuncAttributeMaxDynamicSharedMemorySize, TRI_SMEM);
    cudaFuncSetAttribute(gemmLHW,    cudaFuncAttributeMaxDynamicSharedMemorySize, G2_SMEM);

    // ---- fork: spine B (Z/G/reduce/WWo/chol/finalize/trisolve) on side stream ----
    cudaEventRecord(g_sr.evFork, 0);
    cudaStreamWaitEvent(g_sr.s2, g_sr.evFork, 0);

    compute_Z<<<dim3(128, KHOP), 256, zsmem, g_sr.s2>>>(hop, Wst);
    compute_G<<<dim3(32, KHOP), 256, 0, g_sr.s2>>>();
    reduce_G<<<dim3(KHOP, 16), 256, 0, g_sr.s2>>>();
    computeWWo<<<dim3(KHOP, 4), 256, 0, g_sr.s2>>>(Wst, Wout);
    chol_factor<<<KHOP, 256, 0, g_sr.s2>>>();
    finalize_w<<<1, 32, 0, g_sr.s2>>>(tau, out_tail);
    trisolve_B<<<KHOP, 128, TRI_SMEM, g_sr.s2>>>();
    cudaEventRecord(g_sr.evJoin, g_sr.s2);

    // ---- spine A (HW -> big gemm) on main stream ----
    computeHW<<<128, 256>>>(H, Wout);
    gemmLHW<<<dim3(2, 128), 256, G2_SMEM>>>(L, d_HW, d_LHWp);

    // ---- join, then fused epilogue ----
    cudaStreamWaitEvent(0, g_sr.evJoin, 0);
    fuse_out<<<128, 256>>>(thr, gam, bet, out);
}

// round 13
// speedup vs baseline: 1.5553x; 1.0023x over previous
#include <cuda_runtime.h>
#include <cstdint>
#include <math.h>

// ---------------- problem constants ----------------
#define NN      8192
#define FDIM    256
#define DSUB    64
#define KHOP    3
#define ODIM    128
#define COEFF   0.03125f           // d/(n*eps^2) = 64/(8192*0.25)
#define ETA_C   0.5f
#define LAPSC   0.15f              // ETA*LAMBDA_LAP
#define LN_EPSF 1e-5f

// ---------------- device scratch (no allocs allowed) ----------------
__device__ float g_Z[KHOP][NN][DSUB];           // 6.3 MB
__device__ float g_Gpart[KHOP][32][DSUB*DSUB];  // 1.6 MB
__device__ float g_G[KHOP][DSUB*DSUB];          // reduced Gram (=M)
__device__ float g_R[KHOP];
__device__ float g_s[KHOP];                     // ETA*coeff*w[k]
__device__ float g_Lf[KHOP][DSUB*65];           // Chol factor, diag = 1/sqrt
__device__ float g_WWop[KHOP][4][DSUB][ODIM];   // partial W[k] @ Wout^T
__device__ float g_Bs[KHOP][DSUB][ODIM];        // s_k * M^{-1} WWo
__device__ float g_HW[NN*ODIM];                 // H @ Wout^T   (4 MB)
__device__ float g_LHWp[2][NN*ODIM];            // split-K partials of L @ HW (8 MB)

// ---------------- streams/events created at load time ----------------
struct StreamRes {
    cudaStream_t s2;
    cudaEvent_t evFork, evJoin;
    StreamRes() {
        cudaStreamCreateWithFlags(&s2, cudaStreamNonBlocking);
        cudaEventCreateWithFlags(&evFork, cudaEventDisableTiming);
        cudaEventCreateWithFlags(&evJoin, cudaEventDisableTiming);
    }
};
static StreamRes g_sr;

// ============================================================
// 1) HW = H @ Wout^T  [8192 x 128, K=256]
// ============================================================
__global__ __launch_bounds__(256) void computeHW(const float* __restrict__ H,
                                                 const float* __restrict__ Wout) {
    __shared__ float sAt[16][68];
    __shared__ float sB[16][132];
    const int tid = threadIdx.x;
    const int tx = tid & 15, ty = tid >> 4;
    const int r0 = blockIdx.x * 64;
    float acc[4][8] = {};

    for (int f0 = 0; f0 < FDIM; f0 += 16) {
        int ar = tid >> 2, ac = (tid & 3) * 4;
        float4 a = *(const float4*)&H[(size_t)(r0 + ar) * FDIM + f0 + ac];
        sAt[ac + 0][ar] = a.x; sAt[ac + 1][ar] = a.y;
        sAt[ac + 2][ar] = a.z; sAt[ac + 3][ar] = a.w;
        int bo = tid >> 1, bf = (tid & 1) * 8;
        const float* wpp = Wout + (size_t)bo * FDIM + f0 + bf;
        float4 b1 = *(const float4*)wpp;
        float4 b2 = *(const float4*)(wpp + 4);
        sB[bf + 0][bo] = b1.x; sB[bf + 1][bo] = b1.y;
        sB[bf + 2][bo] = b1.z; sB[bf + 3][bo] = b1.w;
        sB[bf + 4][bo] = b2.x; sB[bf + 5][bo] = b2.y;
        sB[bf + 6][bo] = b2.z; sB[bf + 7][bo] = b2.w;
        __syncthreads();
        #pragma unroll
        for (int kk = 0; kk < 16; kk++) {
            float ra[4], rb[8];
            *(float4*)&ra[0] = *(const float4*)&sAt[kk][ty * 4];
            *(float4*)&rb[0] = *(const float4*)&sB[kk][tx * 8];
            *(float4*)&rb[4] = *(const float4*)&sB[kk][tx * 8 + 4];
            #pragma unroll
            for (int i = 0; i < 4; i++)
                #pragma unroll
                for (int j = 0; j < 8; j++) acc[i][j] += ra[i] * rb[j];
        }
        __syncthreads();
    }
    #pragma unroll
    for (int i = 0; i < 4; i++) {
        size_t row = r0 + ty * 4 + i;
        *(float4*)&g_HW[row * ODIM + tx * 8]     = make_float4(acc[i][0], acc[i][1], acc[i][2], acc[i][3]);
        *(float4*)&g_HW[row * ODIM + tx * 8 + 4] = make_float4(acc[i][4], acc[i][5], acc[i][6], acc[i][7]);
    }
}

// ============================================================
// 2) Z[k] = hop_feats[k] @ W[k]^T
// ============================================================
__global__ __launch_bounds__(256) void compute_Z(const float* __restrict__ hop,
                                                 const float* __restrict__ Wst) {
    extern __shared__ float sm[];
    float* sH = sm;               // [64][257]
    float* sW = sm + 64 * 257;    // [64][257]
    const int tid = threadIdx.x;
    const int k = blockIdx.y;
    const int r0 = blockIdx.x * 64;

    const float* hp = hop + ((size_t)k * NN + r0) * FDIM;
    const float* wp = Wst + (size_t)k * DSUB * FDIM;
    for (int idx = tid * 4; idx < 64 * FDIM; idx += 1024) {
        int r = idx >> 8, c = idx & 255;
        float4 v = *(const float4*)(hp + idx);
        sH[r * 257 + c + 0] = v.x; sH[r * 257 + c + 1] = v.y;
        sH[r * 257 + c + 2] = v.z; sH[r * 257 + c + 3] = v.w;
        float4 w = *(const float4*)(wp + idx);
        sW[r * 257 + c + 0] = w.x; sW[r * 257 + c + 1] = w.y;
        sW[r * 257 + c + 2] = w.z; sW[r * 257 + c + 3] = w.w;
    }
    __syncthreads();

    const int tx = tid & 15, ty = tid >> 4;
    float acc[4][4] = {};
    #pragma unroll 4
    for (int f = 0; f < FDIM; f++) {
        float a[4], b[4];
        #pragma unroll
        for (int i = 0; i < 4; i++) a[i] = sH[(ty * 4 + i) * 257 + f];
        #pragma unroll
        for (int j = 0; j < 4; j++) b[j] = sW[(tx * 4 + j) * 257 + f];
        #pragma unroll
        for (int i = 0; i < 4; i++)
            #pragma unroll
            for (int j = 0; j < 4; j++) acc[i][j] += a[i] * b[j];
    }
    #pragma unroll
    for (int i = 0; i < 4; i++) {
        float4 o = make_float4(acc[i][0], acc[i][1], acc[i][2], acc[i][3]);
        *(float4*)&g_Z[k][r0 + ty * 4 + i][tx * 4] = o;
    }
}

// ============================================================
// 3) partial Gram: each block (32 per k) does 256 rows of Z^T Z
// ============================================================
__global__ __launch_bounds__(256) void compute_G(void) {
    __shared__ float sZ[16 * DSUB];
    const int tid = threadIdx.x;
    const int k = blockIdx.y;
    const int r0 = blockIdx.x * 256;
    const int tx = tid & 15, ty = tid >> 4;
    float acc[4][4] = {};

    for (int chunk = 0; chunk < 256; chunk += 16) {
        int lr = tid >> 4, lc = (tid & 15) * 4;
        *(float4*)&sZ[lr * DSUB + lc] = *(const float4*)&g_Z[k][r0 + chunk + lr][lc];
        __syncthreads();
        #pragma unroll
        for (int rr = 0; rr < 16; rr++) {
            float4 a = *(const float4*)&sZ[rr * DSUB + ty * 4];
            float4 b = *(const float4*)&sZ[rr * DSUB + tx * 4];
            float av[4] = {a.x, a.y, a.z, a.w};
            float bv[4] = {b.x, b.y, b.z, b.w};
            #pragma unroll
            for (int i = 0; i < 4; i++)
                #pragma unroll
                for (int j = 0; j < 4; j++) acc[i][j] += av[i] * bv[j];
        }
        __syncthreads();
    }
    #pragma unroll
    for (int i = 0; i < 4; i++)
        #pragma unroll
        for (int j = 0; j < 4; j++)
            g_Gpart[k][blockIdx.x][(ty * 4 + i) * DSUB + tx * 4 + j] = acc[i][j];
}

// ============================================================
// 3b) reduce_G: grid (KHOP, 16) x 256 thr; one element per thread
// ============================================================
__global__ __launch_bounds__(256) void reduce_G(void) {
    const int k = blockIdx.x;
    const int idx = blockIdx.y * 256 + threadIdx.x;   // 0..4095
    float s = 0.f;
    #pragma unroll
    for (int b = 0; b < 32; b++) s += g_Gpart[k][b][idx];
    int i = idx >> 6, j = idx & 63;
    g_G[k][idx] = (i == j ? 1.f : 0.f) + COEFF * s;   // M = I + coeff*G
}

// ============================================================
// 4) LHWp[kh] = L[:, kh-half] @ HW[kh-half, :] ; tf32 mma + cp.async
//    fragment loads software-pipelined (double-buffered regs)
// ============================================================
#define APAD 36
#define BPAD 136
#define ASTG (64 * APAD)               // 2304 floats (9216 B)
#define BSTG (32 * BPAD)               // 4352 floats (17408 B)
#define STGF (ASTG + BSTG)             // 6656 floats (26624 B)
#define NSTAGE 4
#define G2_SMEM (NSTAGE * STGF * 4)    // 106496 B
#define KHALF (NN / 2)                 // 4096

__device__ __forceinline__ void mma_tf32_16x8x8(float* c, const uint32_t* a,
                                                const uint32_t* b) {
    asm volatile(
        "mma.sync.aligned.m16n8k8.row.col.f32.tf32.tf32.f32 "
        "{%0,%1,%2,%3}, {%4,%5,%6,%7}, {%8,%9}, {%0,%1,%2,%3};"
        : "+f"(c[0]), "+f"(c[1]), "+f"(c[2]), "+f"(c[3])
        : "r"(a[0]), "r"(a[1]), "r"(a[2]), "r"(a[3]), "r"(b[0]), "r"(b[1]));
}

__global__ __launch_bounds__(256, 2) void gemmLHW(const float* __restrict__ L,
                                                  const float* __restrict__ HW,
                                                  float* __restrict__ LHWp) {
    extern __shared__ float smx[];
    uint32_t sb;
    asm("{ .reg .u64 t; cvta.to.shared.u64 t, %1; cvt.u32.u64 %0, t; }"
        : "=r"(sb) : "l"(smx));

    const int tid = threadIdx.x;
    const int lane = tid & 31;
    const int warp = tid >> 5;
    const int g = lane >> 2, t = lane & 3;
    const int wm = (warp & 1) * 32;
    const int wn = (warp >> 1) * 32;
    const int m0 = blockIdx.y * 64;
    const int kh = blockIdx.x;                    // 0 or 1
    const size_t koff = (size_t)kh * KHALF;

    const int ar0 = tid >> 3, ac0 = (tid & 7) * 4;   // A rows ar0, ar0+32
    const int br0 = tid >> 5, bc0 = (tid & 31) * 4;  // B rows br0+8q

    auto issue = [&](int stg) {
        const uint32_t st = sb + (uint32_t)(stg & (NSTAGE - 1)) * (STGF * 4);
        const float* As = L + (size_t)(m0 + ar0) * NN + koff + (size_t)stg * 32 + ac0;
        #pragma unroll
        for (int q = 0; q < 2; q++) {
            uint32_t d = st + (uint32_t)((ar0 + q * 32) * APAD + ac0) * 4u;
            asm volatile("cp.async.cg.shared.global [%0], [%1], 16;"
                         :: "r"(d), "l"(As + (size_t)q * 32 * NN) : "memory");
        }
        const float* Bs = HW + (koff + (size_t)stg * 32 + br0) * ODIM + bc0;
        const uint32_t bb = st + ASTG * 4u;
        #pragma unroll
        for (int q = 0; q < 4; q++) {
            uint32_t d = bb + (uint32_t)((br0 + q * 8) * BPAD + bc0) * 4u;
            asm volatile("cp.async.cg.shared.global [%0], [%1], 16;"
                         :: "r"(d), "l"(Bs + (size_t)q * 8 * ODIM) : "memory");
        }
    };

    #pragma unroll
    for (int s = 0; s < NSTAGE - 1; s++) {
        issue(s);
        asm volatile("cp.async.commit_group;" ::: "memory");
    }

    float acc[2][4][4] = {};
    const int NITER = KHALF / 32;   // 128

    uint32_t afr[2][2][4], bfr[2][4][2];   // double-buffered fragments

    for (int it = 0; it < NITER; it++) {
        asm volatile("cp.async.wait_group %0;" :: "n"(NSTAGE - 2) : "memory");
        __syncthreads();
        int nx = it + NSTAGE - 1;
        if (nx < NITER) issue(nx);
        asm volatile("cp.async.commit_group;" ::: "memory");

        const float* pa = smx + (it & (NSTAGE - 1)) * STGF;
        const float* pb = pa + ASTG;
        const uint32_t* ua = (const uint32_t*)pa;
        const uint32_t* ub = (const uint32_t*)pb;

        // load fragments for ks=0
        {
            const int kk = t;
            #pragma unroll
            for (int mt = 0; mt < 2; mt++) {
                const int r = wm + mt * 16 + g;
                afr[0][mt][0] = ua[r * APAD + kk];
                afr[0][mt][1] = ua[(r + 8) * APAD + kk];
                afr[0][mt][2] = ua[r * APAD + kk + 4];
                afr[0][mt][3] = ua[(r + 8) * APAD + kk + 4];
            }
            #pragma unroll
            for (int nt = 0; nt < 4; nt++) {
                const int n = wn + nt * 8 + g;
                bfr[0][nt][0] = ub[kk * BPAD + n];
                bfr[0][nt][1] = ub[(kk + 4) * BPAD + n];
            }
        }
        #pragma unroll
        for (int ks = 0; ks < 4; ks++) {
            // prefetch fragments for ks+1 while MMAs of ks run
            if (ks < 3) {
                const int kk = (ks + 1) * 8 + t;
                const int nb = (ks + 1) & 1;
                #pragma unroll
                for (int mt = 0; mt < 2; mt++) {
                    const int r = wm + mt * 16 + g;
                    afr[nb][mt][0] = ua[r * APAD + kk];
                    afr[nb][mt][1] = ua[(r + 8) * APAD + kk];
                    afr[nb][mt][2] = ua[r * APAD + kk + 4];
                    afr[nb][mt][3] = ua[(r + 8) * APAD + kk + 4];
                }
                #pragma unroll
                for (int nt = 0; nt < 4; nt++) {
                    const int n = wn + nt * 8 + g;
                    bfr[nb][nt][0] = ub[kk * BPAD + n];
                    bfr[nb][nt][1] = ub[(kk + 4) * BPAD + n];
                }
            }
            const int cb = ks & 1;
            #pragma unroll
            for (int mt = 0; mt < 2; mt++)
                #pragma unroll
                for (int nt = 0; nt < 4; nt++)
                    mma_tf32_16x8x8(acc[mt][nt], afr[cb][mt], bfr[cb][nt]);
        }
    }

    float* outp = LHWp + (size_t)kh * NN * ODIM;
    const int er = g, ec = t * 2;
    #pragma unroll
    for (int mt = 0; mt < 2; mt++) {
        #pragma unroll
        for (int nt = 0; nt < 4; nt++) {
            const int row = m0 + wm + mt * 16 + er;
            const int col = wn + nt * 8 + ec;
            *(float2*)&outp[(size_t)row * ODIM + col] =
                make_float2(acc[mt][nt][0], acc[mt][nt][1]);
            *(float2*)&outp[(size_t)(row + 8) * ODIM + col] =
                make_float2(acc[mt][nt][2], acc[mt][nt][3]);
        }
    }
}

// ============================================================
// 5) WWo partials: grid (KHOP, 4); each CTA does 64 f-values
// ============================================================
__global__ __launch_bounds__(256) void computeWWo(const float* __restrict__ Wst,
                                                  const float* __restrict__ Wout) {
    __shared__ float sAt[16][68];
    __shared__ float sB[16][132];
    const int tid = threadIdx.x;
    const int tx = tid & 15, ty = tid >> 4;
    const int k = blockIdx.x;
    const int fbase = blockIdx.y * 64;
    float acc[4][8] = {};

    for (int fo = 0; fo < 64; fo += 16) {
        int f0 = fbase + fo;
        int ar = tid >> 2, ac = (tid & 3) * 4;
        float4 a = *(const float4*)&Wst[((size_t)k * DSUB + ar) * FDIM + f0 + ac];
        sAt[ac + 0][ar] = a.x; sAt[ac + 1][ar] = a.y;
        sAt[ac + 2][ar] = a.z; sAt[ac + 3][ar] = a.w;
        int bo = tid >> 1, bf = (tid & 1) * 8;
        const float* wpp = Wout + (size_t)bo * FDIM + f0 + bf;
        float4 b1 = *(const float4*)wpp;
        float4 b2 = *(const float4*)(wpp + 4);
        sB[bf + 0][bo] = b1.x; sB[bf + 1][bo] = b1.y;
        sB[bf + 2][bo] = b1.z; sB[bf + 3][bo] = b1.w;
        sB[bf + 4][bo] = b2.x; sB[bf + 5][bo] = b2.y;
        sB[bf + 6][bo] = b2.z; sB[bf + 7][bo] = b2.w;
        __syncthreads();
        #pragma unroll
        for (int kk = 0; kk < 16; kk++) {
            float ra[4], rb[8];
            *(float4*)&ra[0] = *(const float4*)&sAt[kk][ty * 4];
            *(float4*)&rb[0] = *(const float4*)&sB[kk][tx * 8];
            *(float4*)&rb[4] = *(const float4*)&sB[kk][tx * 8 + 4];
            #pragma unroll
            for (int i = 0; i < 4; i++)
                #pragma unroll
                for (int j = 0; j < 8; j++) acc[i][j] += ra[i] * rb[j];
        }
        __syncthreads();
    }
    #pragma unroll
    for (int i = 0; i < 4; i++) {
        int d = ty * 4 + i;
        *(float4*)&g_WWop[k][blockIdx.y][d][tx * 8]     = make_float4(acc[i][0], acc[i][1], acc[i][2], acc[i][3]);
        *(float4*)&g_WWop[k][blockIdx.y][d][tx * 8 + 4] = make_float4(acc[i][4], acc[i][5], acc[i][6], acc[i][7]);
    }
}

// ============================================================
// 6) chol_factor: loads pre-reduced M, blocked right-looking factor
// ============================================================
__global__ __launch_bounds__(256) void chol_factor(void) {
    __shared__ float sM[DSUB * 65];
    __shared__ float sD[DSUB];
    const int k = blockIdx.x, tid = threadIdx.x;
    const int lane = tid & 31;
    const int warp = tid >> 5;

    for (int idx = tid; idx < DSUB * DSUB; idx += 256) {
        int i = idx >> 6, j = idx & 63;
        sM[i * 65 + j] = g_G[k][idx];
    }
    __syncthreads();

    const int ui = tid >> 2;          // trailing-update row 0..63
    const int ub = tid & 3;           // trailing-update col base
    for (int p0 = 0; p0 < DSUB; p0 += 8) {
        if (warp == 0) {
            #pragma unroll
            for (int jj = 0; jj < 8; jj++) {
                const int j = p0 + jj;
                float d = sM[j * 65 + j];
                float dinv = rsqrtf(d);
                if (lane == 0) sD[j] = d;
                #pragma unroll
                for (int h = 0; h < 2; h++) {
                    int i = lane + h * 32;
                    if (i > j) sM[i * 65 + j] *= dinv;
                }
                __syncwarp();
                for (int p = j + 1; p < p0 + 8; p++) {
                    float cp = sM[p * 65 + j];
                    #pragma unroll
                    for (int h = 0; h < 2; h++) {
                        int i = lane + h * 32;
                        if (i >= p) sM[i * 65 + p] -= sM[i * 65 + j] * cp;
                    }
                    __syncwarp();
                }
                if (lane == 0) sM[j * 65 + j] = dinv;   // diag := 1/sqrt for solver
                __syncwarp();
            }
        }
        __syncthreads();
        const int p1 = p0 + 8;
        if (p1 < DSUB && ui >= p1) {
            float lrow[8];
            #pragma unroll
            for (int jj = 0; jj < 8; jj++) lrow[jj] = sM[ui * 65 + p0 + jj];
            #pragma unroll
            for (int qq = 0; qq < 16; qq++) {
                int c = ub + (qq << 2);
                if (c >= p1 && c <= ui) {
                    float s = 0.f;
                    #pragma unroll
                    for (int jj = 0; jj < 8; jj++)
                        s += lrow[jj] * sM[c * 65 + p0 + jj];
                    sM[ui * 65 + c] -= s;
                }
            }
        }
        __syncthreads();
    }

    if (tid == 0) {
        float r = 0.f;
        #pragma unroll 4
        for (int j = 0; j < DSUB; j++) r += logf(sD[j]);
        g_R[k] = 0.5f * r;
    }
    __syncthreads();
    for (int idx = tid; idx < DSUB * 65; idx += 256) g_Lf[k][idx] = sM[idx];
}

// ============================================================
// 7) finalize softmax weights + output tail
// ============================================================
__global__ void finalize_w(const float* __restrict__ taup, float* __restrict__ out_tail) {
    if (threadIdx.x != 0) return;
    float R0 = g_R[0], R1 = g_R[1], R2 = g_R[2];
    float d0 = R0, d1 = R1 - R0, d2 = R2 - R1;
    float mean = (d0 + d1 + d2) * (1.f / 3.f);
    float e0 = d0 - mean, e1 = d1 - mean, e2 = d2 - mean;
    float sd = sqrtf((e0 * e0 + e1 * e1 + e2 * e2) * 0.5f);   // ddof=1
    float s = 1.f / (sd + 1e-6f);
    float n0 = e0 * s, n1 = e1 * s, n2 = e2 * s;
    float tau = taup[0];
    float a0 = n0 / tau, a1 = n1 / tau, a2 = n2 / tau;
    float mx = fmaxf(a0, fmaxf(a1, a2));
    float x0 = expf(a0 - mx), x1 = expf(a1 - mx), x2 = expf(a2 - mx);
    float isum = 1.f / (x0 + x1 + x2);
    float w0 = x0 * isum, w1 = x1 * isum, w2 = x2 * isum;
    out_tail[0] = w0; out_tail[1] = w1; out_tail[2] = w2;
    out_tail[3] = n0; out_tail[4] = n1; out_tail[5] = n2;
    out_tail[6] = d0; out_tail[7] = d1; out_tail[8] = d2;
    g_s[0] = ETA_C * COEFF * w0;
    g_s[1] = ETA_C * COEFF * w1;
    g_s[2] = ETA_C * COEFF * w2;
}

// ============================================================
// 8) trisolve: Bs[k] = s_k * M^{-1} (sum WWop)   (128 RHS)
// ============================================================
#define TRI_SMEM ((DSUB * 65 + DSUB * 132) * 4)
__global__ __launch_bounds__(128) void trisolve_B(void) {
    extern __shared__ float tsm[];
    float* sL = tsm;                  // [64][65], diag = 1/sqrt
    float* sY = tsm + DSUB * 65;      // [64][132]
    const int k = blockIdx.x, c = threadIdx.x;

    for (int idx = c; idx < DSUB * 65; idx += 128) sL[idx] = g_Lf[k][idx];
    __syncthreads();

    const float sk = g_s[k];
    for (int i = 0; i < DSUB; i++) {
        float s = g_WWop[k][0][i][c] + g_WWop[k][1][i][c]
                + g_WWop[k][2][i][c] + g_WWop[k][3][i][c];
        float s0 = 0.f, s1 = 0.f, s2 = 0.f, s3 = 0.f;
        int j = 0;
        for (; j + 4 <= i; j += 4) {
            s0 += sL[i * 65 + j + 0] * sY[(j + 0) * 132 + c];
            s1 += sL[i * 65 + j + 1] * sY[(j + 1) * 132 + c];
            s2 += sL[i * 65 + j + 2] * sY[(j + 2) * 132 + c];
            s3 += sL[i * 65 + j + 3] * sY[(j + 3) * 132 + c];
        }
        for (; j < i; j++) s0 += sL[i * 65 + j] * sY[j * 132 + c];
        sY[i * 132 + c] = (s - ((s0 + s1) + (s2 + s3))) * sL[i * 65 + i];
    }
    for (int i = DSUB - 1; i >= 0; i--) {
        float s = sY[i * 132 + c];
        float s0 = 0.f, s1 = 0.f, s2 = 0.f, s3 = 0.f;
        int j = i + 1;
        for (; j + 4 <= DSUB; j += 4) {
            s0 += sL[(j + 0) * 65 + i] * sY[(j + 0) * 132 + c];
            s1 += sL[(j + 1) * 65 + i] * sY[(j + 1) * 132 + c];
            s2 += sL[(j + 2) * 65 + i] * sY[(j + 2) * 132 + c];
            s3 += sL[(j + 3) * 65 + i] * sY[(j + 3) * 132 + c];
        }
        for (; j < DSUB; j++) s0 += sL[j * 65 + i] * sY[j * 132 + c];
        float x = (s - ((s0 + s1) + (s2 + s3))) * sL[i * 65 + i];
        sY[i * 132 + c] = x;
        g_Bs[k][i][c] = sk * x;
    }
}

// ============================================================
// 9) H_pre = HW + sum_k Z_k @ Bs_k - 0.15*(LHWp0+LHWp1) ; soft-thr ; LN
// ============================================================
__global__ __launch_bounds__(256) void fuse_out(const float* __restrict__ thrP,
                                                const float* __restrict__ gamP,
                                                const float* __restrict__ betP,
                                                float* __restrict__ out) {
    __shared__ float sAt[16][68];   // Z chunk transposed [d][row]
    __shared__ float sB[16][132];   // Bs chunk [d][col]
    const int tid = threadIdx.x;
    const int tx = tid & 15, ty = tid >> 4;
    const int r0 = blockIdx.x * 64;
    float acc[4][8] = {};

    for (int k = 0; k < KHOP; k++) {
        for (int d0 = 0; d0 < DSUB; d0 += 16) {
            int ar = tid >> 2, ac = (tid & 3) * 4;
            float4 a = *(const float4*)&g_Z[k][r0 + ar][d0 + ac];
            sAt[ac + 0][ar] = a.x; sAt[ac + 1][ar] = a.y;
            sAt[ac + 2][ar] = a.z; sAt[ac + 3][ar] = a.w;
            int dl = tid >> 4, c8 = (tid & 15) * 8;
            float4 b1 = *(const float4*)&g_Bs[k][d0 + dl][c8];
            float4 b2 = *(const float4*)&g_Bs[k][d0 + dl][c8 + 4];
            *(float4*)&sB[dl][c8]     = b1;
            *(float4*)&sB[dl][c8 + 4] = b2;
            __syncthreads();
            #pragma unroll
            for (int kk = 0; kk < 16; kk++) {
                float ra[4], rb[8];
                *(float4*)&ra[0] = *(const float4*)&sAt[kk][ty * 4];
                *(float4*)&rb[0] = *(const float4*)&sB[kk][tx * 8];
                *(float4*)&rb[4] = *(const float4*)&sB[kk][tx * 8 + 4];
                #pragma unroll
                for (int i = 0; i < 4; i++)
                    #pragma unroll
                    for (int j = 0; j < 8; j++) acc[i][j] += ra[i] * rb[j];
            }
            __syncthreads();
        }
    }

    float thr_[8], gam_[8], bet_[8];
    #pragma unroll
    for (int j = 0; j < 8; j++) {
        int c = tx * 8 + j;
        thr_[j] = fabsf(__ldg(&thrP[c]));
        gam_[j] = __ldg(&gamP[c]);
        bet_[j] = __ldg(&betP[c]);
    }
    #pragma unroll
    for (int i = 0; i < 4; i++) {
        size_t row = r0 + ty * 4 + i;
        float4 hw1 = *(const float4*)&g_HW[row * ODIM + tx * 8];
        float4 hw2 = *(const float4*)&g_HW[row * ODIM + tx * 8 + 4];
        float4 p1a = *(const float4*)&g_LHWp[0][row * ODIM + tx * 8];
        float4 p1b = *(const float4*)&g_LHWp[0][row * ODIM + tx * 8 + 4];
        float4 p2a = *(const float4*)&g_LHWp[1][row * ODIM + tx * 8];
        float4 p2b = *(const float4*)&g_LHWp[1][row * ODIM + tx * 8 + 4];
        float bias[8] = {hw1.x - LAPSC * (p1a.x + p2a.x), hw1.y - LAPSC * (p1a.y + p2a.y),
                         hw1.z - LAPSC * (p1a.z + p2a.z), hw1.w - LAPSC * (p1a.w + p2a.w),
                         hw2.x - LAPSC * (p1b.x + p2b.x), hw2.y - LAPSC * (p1b.y + p2b.y),
                         hw2.z - LAPSC * (p1b.z + p2b.z), hw2.w - LAPSC * (p1b.w + p2b.w)};
        float v[8], s = 0.f, q = 0.f;
        #pragma unroll
        for (int j = 0; j < 8; j++) {
            float p = acc[i][j] + bias[j];
            float ap = fabsf(p) - thr_[j];
            float val = ap > 0.f ? copysignf(ap, p) : 0.f;
            v[j] = val; s += val; q += val * val;
        }
        #pragma unroll
        for (int o = 8; o >= 1; o >>= 1) {
            s += __shfl_xor_sync(0xffffffffu, s, o);
            q += __shfl_xor_sync(0xffffffffu, q, o);
        }
        float mu = s * (1.f / 128.f);
        float var = q * (1.f / 128.f) - mu * mu;
        float rs = rsqrtf(var + LN_EPSF);
        float o_[8];
        #pragma unroll
        for (int j = 0; j < 8; j++) o_[j] = (v[j] - mu) * rs * gam_[j] + bet_[j];
        *(float4*)&out[row * ODIM + tx * 8]     = make_float4(o_[0], o_[1], o_[2], o_[3]);
        *(float4*)&out[row * ODIM + tx * 8 + 4] = make_float4(o_[4], o_[5], o_[6], o_[7]);
    }
}

// ============================================================
extern "C" void kernel_launch(void* const* d_in, const int* in_sizes, int n_in,
                              void* d_out, int out_size) {
    const float* H    = (const float*)d_in[0];
    const float* hop  = (const float*)d_in[1];
    const float* L    = (const float*)d_in[2];
    const float* Wst  = (const float*)d_in[3];
    const float* Wout = (const float*)d_in[4];
    const float* thr  = (const float*)d_in[5];
    const float* gam  = (const float*)d_in[6];
    const float* bet  = (const float*)d_in[7];
    const float* tau  = (const float*)d_in[8];
    float* out = (float*)d_out;
    float* out_tail = out + (size_t)NN * ODIM;

    float* d_HW;
    cudaGetSymbolAddress((void**)&d_HW, g_HW);
    float* d_LHWp;
    cudaGetSymbolAddress((void**)&d_LHWp, g_LHWp);

    const int zsmem = 2 * 64 * 257 * 4;                           // 131584
    cudaFuncSetAttribute(compute_Z,  cudaFuncAttributeMaxDynamicSharedMemorySize, zsmem);
    cudaFuncSetAttribute(trisolve_B, cudaFuncAttributeMaxDynamicSharedMemorySize, TRI_SMEM);
    cudaFuncSetAttribute(gemmLHW,    cudaFuncAttributeMaxDynamicSharedMemorySize, G2_SMEM);

    // ---- fork: spine B (Z/G/reduce/WWo/chol/finalize/trisolve) on side stream ----
    cudaEventRecord(g_sr.evFork, 0);
    cudaStreamWaitEvent(g_sr.s2, g_sr.evFork, 0);

    compute_Z<<<dim3(128, KHOP), 256, zsmem, g_sr.s2>>>(hop, Wst);
    compute_G<<<dim3(32, KHOP), 256, 0, g_sr.s2>>>();
    reduce_G<<<dim3(KHOP, 16), 256, 0, g_sr.s2>>>();
    computeWWo<<<dim3(KHOP, 4), 256, 0, g_sr.s2>>>(Wst, Wout);
    chol_factor<<<KHOP, 256, 0, g_sr.s2>>>();
    finalize_w<<<1, 32, 0, g_sr.s2>>>(tau, out_tail);
    trisolve_B<<<KHOP, 128, TRI_SMEM, g_sr.s2>>>();
    cudaEventRecord(g_sr.evJoin, g_sr.s2);

    // ---- spine A (HW -> big gemm) on main stream ----
    computeHW<<<128, 256>>>(H, Wout);
    gemmLHW<<<dim3(2, 128), 256, G2_SMEM>>>(L, d_HW, d_LHWp);

    // ---- join, then fused epilogue ----
    cudaStreamWaitEvent(0, g_sr.evJoin, 0);
    fuse_out<<<128, 256>>>(thr, gam, bet, out);
}

// round 14
// speedup vs baseline: 1.8778x; 1.2074x over previous
#include <cuda_runtime.h>
#include <cstdint>
#include <math.h>

// ---------------- problem constants ----------------
#define NN      8192
#define FDIM    256
#define DSUB    64
#define KHOP    3
#define ODIM    128
#define COEFF   0.03125f           // d/(n*eps^2) = 64/(8192*0.25)
#define ETA_C   0.5f
#define LAPSC   0.15f              // ETA*LAMBDA_LAP
#define LN_EPSF 1e-5f

// ---------------- device scratch (no allocs allowed) ----------------
__device__ float g_Z[KHOP][NN][DSUB];           // 6.3 MB
__device__ float g_Gpart[KHOP][32][DSUB*DSUB];  // 1.6 MB
__device__ float g_G[KHOP][DSUB*DSUB];          // reduced Gram (=M)
__device__ float g_R[KHOP];
__device__ float g_s[KHOP];                     // ETA*coeff*w[k]
__device__ float g_Lf[KHOP][DSUB*65];           // Chol factor, diag = 1/sqrt
__device__ float g_WWop[KHOP][4][DSUB][ODIM];   // partial W[k] @ Wout^T
__device__ float g_Bs[KHOP][DSUB][ODIM];        // s_k * M^{-1} WWo
__device__ float g_HW[NN*ODIM];                 // H @ Wout^T   (4 MB)
__device__ float g_LHWp[2][NN*ODIM];            // split-K partials of L @ HW (8 MB)

// ---------------- streams/events created at load time ----------------
struct StreamRes {
    cudaStream_t s2;
    cudaEvent_t evFork, evJoin;
    StreamRes() {
        cudaStreamCreateWithFlags(&s2, cudaStreamNonBlocking);
        cudaEventCreateWithFlags(&evFork, cudaEventDisableTiming);
        cudaEventCreateWithFlags(&evJoin, cudaEventDisableTiming);
    }
};
static StreamRes g_sr;

// ============================================================
// 1) HW = H @ Wout^T  [8192 x 128, K=256]
// ============================================================
__global__ __launch_bounds__(256) void computeHW(const float* __restrict__ H,
                                                 const float* __restrict__ Wout) {
    __shared__ float sAt[16][68];
    __shared__ float sB[16][132];
    const int tid = threadIdx.x;
    const int tx = tid & 15, ty = tid >> 4;
    const int r0 = blockIdx.x * 64;
    float acc[4][8] = {};

    for (int f0 = 0; f0 < FDIM; f0 += 16) {
        int ar = tid >> 2, ac = (tid & 3) * 4;
        float4 a = *(const float4*)&H[(size_t)(r0 + ar) * FDIM + f0 + ac];
        sAt[ac + 0][ar] = a.x; sAt[ac + 1][ar] = a.y;
        sAt[ac + 2][ar] = a.z; sAt[ac + 3][ar] = a.w;
        int bo = tid >> 1, bf = (tid & 1) * 8;
        const float* wpp = Wout + (size_t)bo * FDIM + f0 + bf;
        float4 b1 = *(const float4*)wpp;
        float4 b2 = *(const float4*)(wpp + 4);
        sB[bf + 0][bo] = b1.x; sB[bf + 1][bo] = b1.y;
        sB[bf + 2][bo] = b1.z; sB[bf + 3][bo] = b1.w;
        sB[bf + 4][bo] = b2.x; sB[bf + 5][bo] = b2.y;
        sB[bf + 6][bo] = b2.z; sB[bf + 7][bo] = b2.w;
        __syncthreads();
        #pragma unroll
        for (int kk = 0; kk < 16; kk++) {
            float ra[4], rb[8];
            *(float4*)&ra[0] = *(const float4*)&sAt[kk][ty * 4];
            *(float4*)&rb[0] = *(const float4*)&sB[kk][tx * 8];
            *(float4*)&rb[4] = *(const float4*)&sB[kk][tx * 8 + 4];
            #pragma unroll
            for (int i = 0; i < 4; i++)
                #pragma unroll
                for (int j = 0; j < 8; j++) acc[i][j] += ra[i] * rb[j];
        }
        __syncthreads();
    }
    #pragma unroll
    for (int i = 0; i < 4; i++) {
        size_t row = r0 + ty * 4 + i;
        *(float4*)&g_HW[row * ODIM + tx * 8]     = make_float4(acc[i][0], acc[i][1], acc[i][2], acc[i][3]);
        *(float4*)&g_HW[row * ODIM + tx * 8 + 4] = make_float4(acc[i][4], acc[i][5], acc[i][6], acc[i][7]);
    }
}

// ============================================================
// 2) Z[k] = hop_feats[k] @ W[k]^T  -- low-smem (8.7 KB) version
//    BM=64, BN=64, BK=16; grid (128, KHOP); co-resident with gemm
// ============================================================
__global__ __launch_bounds__(256) void compute_Z(const float* __restrict__ hop,
                                                 const float* __restrict__ Wst) {
    __shared__ float sAt[16][68];   // hop chunk transposed [f][row]
    __shared__ float sW[16][68];    // W chunk [f][d]
    const int tid = threadIdx.x;
    const int tx = tid & 15, ty = tid >> 4;
    const int k = blockIdx.y;
    const int r0 = blockIdx.x * 64;
    float acc[4][4] = {};

    const float* hp = hop + (size_t)k * NN * FDIM;
    const float* wp = Wst + (size_t)k * DSUB * FDIM;

    for (int f0 = 0; f0 < FDIM; f0 += 16) {
        int ar = tid >> 2, ac = (tid & 3) * 4;       // ar = local row/d (0..63)
        float4 a = *(const float4*)&hp[(size_t)(r0 + ar) * FDIM + f0 + ac];
        sAt[ac + 0][ar] = a.x; sAt[ac + 1][ar] = a.y;
        sAt[ac + 2][ar] = a.z; sAt[ac + 3][ar] = a.w;
        float4 w = *(const float4*)&wp[(size_t)ar * FDIM + f0 + ac];
        sW[ac + 0][ar] = w.x; sW[ac + 1][ar] = w.y;
        sW[ac + 2][ar] = w.z; sW[ac + 3][ar] = w.w;
        __syncthreads();
        #pragma unroll
        for (int kk = 0; kk < 16; kk++) {
            float ra[4], rb[4];
            *(float4*)&ra[0] = *(const float4*)&sAt[kk][ty * 4];
            *(float4*)&rb[0] = *(const float4*)&sW[kk][tx * 4];
            #pragma unroll
            for (int i = 0; i < 4; i++)
                #pragma unroll
                for (int j = 0; j < 4; j++) acc[i][j] += ra[i] * rb[j];
        }
        __syncthreads();
    }
    #pragma unroll
    for (int i = 0; i < 4; i++) {
        float4 o = make_float4(acc[i][0], acc[i][1], acc[i][2], acc[i][3]);
        *(float4*)&g_Z[k][r0 + ty * 4 + i][tx * 4] = o;
    }
}

// ============================================================
// 3) partial Gram: each block (32 per k) does 256 rows of Z^T Z
// ============================================================
__global__ __launch_bounds__(256) void compute_G(void) {
    __shared__ float sZ[16 * DSUB];
    const int tid = threadIdx.x;
    const int k = blockIdx.y;
    const int r0 = blockIdx.x * 256;
    const int tx = tid & 15, ty = tid >> 4;
    float acc[4][4] = {};

    for (int chunk = 0; chunk < 256; chunk += 16) {
        int lr = tid >> 4, lc = (tid & 15) * 4;
        *(float4*)&sZ[lr * DSUB + lc] = *(const float4*)&g_Z[k][r0 + chunk + lr][lc];
        __syncthreads();
        #pragma unroll
        for (int rr = 0; rr < 16; rr++) {
            float4 a = *(const float4*)&sZ[rr * DSUB + ty * 4];
            float4 b = *(const float4*)&sZ[rr * DSUB + tx * 4];
            float av[4] = {a.x, a.y, a.z, a.w};
            float bv[4] = {b.x, b.y, b.z, b.w};
            #pragma unroll
            for (int i = 0; i < 4; i++)
                #pragma unroll
                for (int j = 0; j < 4; j++) acc[i][j] += av[i] * bv[j];
        }
        __syncthreads();
    }
    #pragma unroll
    for (int i = 0; i < 4; i++)
        #pragma unroll
        for (int j = 0; j < 4; j++)
            g_Gpart[k][blockIdx.x][(ty * 4 + i) * DSUB + tx * 4 + j] = acc[i][j];
}

// ============================================================
// 3b) reduce_G: grid (KHOP, 16) x 256 thr; one element per thread
// ============================================================
__global__ __launch_bounds__(256) void reduce_G(void) {
    const int k = blockIdx.x;
    const int idx = blockIdx.y * 256 + threadIdx.x;   // 0..4095
    float s = 0.f;
    #pragma unroll
    for (int b = 0; b < 32; b++) s += g_Gpart[k][b][idx];
    int i = idx >> 6, j = idx & 63;
    g_G[k][idx] = (i == j ? 1.f : 0.f) + COEFF * s;   // M = I + coeff*G
}

// ============================================================
// 4) LHWp[kh] = L[:, kh-half] @ HW[kh-half, :] ; tf32 mma + cp.async
// ============================================================
#define APAD 36
#define BPAD 136
#define ASTG (64 * APAD)               // 2304 floats (9216 B)
#define BSTG (32 * BPAD)               // 4352 floats (17408 B)
#define STGF (ASTG + BSTG)             // 6656 floats (26624 B)
#define NSTAGE 4
#define G2_SMEM (NSTAGE * STGF * 4)    // 106496 B
#define KHALF (NN / 2)                 // 4096

__device__ __forceinline__ void mma_tf32_16x8x8(float* c, const uint32_t* a,
                                                const uint32_t* b) {
    asm volatile(
        "mma.sync.aligned.m16n8k8.row.col.f32.tf32.tf32.f32 "
        "{%0,%1,%2,%3}, {%4,%5,%6,%7}, {%8,%9}, {%0,%1,%2,%3};"
        : "+f"(c[0]), "+f"(c[1]), "+f"(c[2]), "+f"(c[3])
        : "r"(a[0]), "r"(a[1]), "r"(a[2]), "r"(a[3]), "r"(b[0]), "r"(b[1]));
}

__global__ __launch_bounds__(256, 2) void gemmLHW(const float* __restrict__ L,
                                                  const float* __restrict__ HW,
                                                  float* __restrict__ LHWp) {
    extern __shared__ float smx[];
    uint32_t sb;
    asm("{ .reg .u64 t; cvta.to.shared.u64 t, %1; cvt.u32.u64 %0, t; }"
        : "=r"(sb) : "l"(smx));

    const int tid = threadIdx.x;
    const int lane = tid & 31;
    const int warp = tid >> 5;
    const int g = lane >> 2, t = lane & 3;
    const int wm = (warp & 1) * 32;
    const int wn = (warp >> 1) * 32;
    const int m0 = blockIdx.y * 64;
    const int kh = blockIdx.x;                    // 0 or 1
    const size_t koff = (size_t)kh * KHALF;

    const int ar0 = tid >> 3, ac0 = (tid & 7) * 4;   // A rows ar0, ar0+32
    const int br0 = tid >> 5, bc0 = (tid & 31) * 4;  // B rows br0+8q

    auto issue = [&](int stg) {
        const uint32_t st = sb + (uint32_t)(stg & (NSTAGE - 1)) * (STGF * 4);
        const float* As = L + (size_t)(m0 + ar0) * NN + koff + (size_t)stg * 32 + ac0;
        #pragma unroll
        for (int q = 0; q < 2; q++) {
            uint32_t d = st + (uint32_t)((ar0 + q * 32) * APAD + ac0) * 4u;
            asm volatile("cp.async.cg.shared.global [%0], [%1], 16;"
                         :: "r"(d), "l"(As + (size_t)q * 32 * NN) : "memory");
        }
        const float* Bs = HW + (koff + (size_t)stg * 32 + br0) * ODIM + bc0;
        const uint32_t bb = st + ASTG * 4u;
        #pragma unroll
        for (int q = 0; q < 4; q++) {
            uint32_t d = bb + (uint32_t)((br0 + q * 8) * BPAD + bc0) * 4u;
            asm volatile("cp.async.cg.shared.global [%0], [%1], 16;"
                         :: "r"(d), "l"(Bs + (size_t)q * 8 * ODIM) : "memory");
        }
    };

    #pragma unroll
    for (int s = 0; s < NSTAGE - 1; s++) {
        issue(s);
        asm volatile("cp.async.commit_group;" ::: "memory");
    }

    float acc[2][4][4] = {};
    const int NITER = KHALF / 32;   // 128

    uint32_t afr[2][2][4], bfr[2][4][2];   // double-buffered fragments

    for (int it = 0; it < NITER; it++) {
        asm volatile("cp.async.wait_group %0;" :: "n"(NSTAGE - 2) : "memory");
        __syncthreads();
        int nx = it + NSTAGE - 1;
        if (nx < NITER) issue(nx);
        asm volatile("cp.async.commit_group;" ::: "memory");

        const float* pa = smx + (it & (NSTAGE - 1)) * STGF;
        const float* pb = pa + ASTG;
        const uint32_t* ua = (const uint32_t*)pa;
        const uint32_t* ub = (const uint32_t*)pb;

        // load fragments for ks=0
        {
            const int kk = t;
            #pragma unroll
            for (int mt = 0; mt < 2; mt++) {
                const int r = wm + mt * 16 + g;
                afr[0][mt][0] = ua[r * APAD + kk];
                afr[0][mt][1] = ua[(r + 8) * APAD + kk];
                afr[0][mt][2] = ua[r * APAD + kk + 4];
                afr[0][mt][3] = ua[(r + 8) * APAD + kk + 4];
            }
            #pragma unroll
            for (int nt = 0; nt < 4; nt++) {
                const int n = wn + nt * 8 + g;
                bfr[0][nt][0] = ub[kk * BPAD + n];
                bfr[0][nt][1] = ub[(kk + 4) * BPAD + n];
            }
        }
        #pragma unroll
        for (int ks = 0; ks < 4; ks++) {
            if (ks < 3) {
                const int kk = (ks + 1) * 8 + t;
                const int nb = (ks + 1) & 1;
                #pragma unroll
                for (int mt = 0; mt < 2; mt++) {
                    const int r = wm + mt * 16 + g;
                    afr[nb][mt][0] = ua[r * APAD + kk];
                    afr[nb][mt][1] = ua[(r + 8) * APAD + kk];
                    afr[nb][mt][2] = ua[r * APAD + kk + 4];
                    afr[nb][mt][3] = ua[(r + 8) * APAD + kk + 4];
                }
                #pragma unroll
                for (int nt = 0; nt < 4; nt++) {
                    const int n = wn + nt * 8 + g;
                    bfr[nb][nt][0] = ub[kk * BPAD + n];
                    bfr[nb][nt][1] = ub[(kk + 4) * BPAD + n];
                }
            }
            const int cb = ks & 1;
            #pragma unroll
            for (int mt = 0; mt < 2; mt++)
                #pragma unroll
                for (int nt = 0; nt < 4; nt++)
                    mma_tf32_16x8x8(acc[mt][nt], afr[cb][mt], bfr[cb][nt]);
        }
    }

    float* outp = LHWp + (size_t)kh * NN * ODIM;
    const int er = g, ec = t * 2;
    #pragma unroll
    for (int mt = 0; mt < 2; mt++) {
        #pragma unroll
        for (int nt = 0; nt < 4; nt++) {
            const int row = m0 + wm + mt * 16 + er;
            const int col = wn + nt * 8 + ec;
            *(float2*)&outp[(size_t)row * ODIM + col] =
                make_float2(acc[mt][nt][0], acc[mt][nt][1]);
            *(float2*)&outp[(size_t)(row + 8) * ODIM + col] =
                make_float2(acc[mt][nt][2], acc[mt][nt][3]);
        }
    }
}

// ============================================================
// 5) WWo partials: grid (KHOP, 4); each CTA does 64 f-values
// ============================================================
__global__ __launch_bounds__(256) void computeWWo(const float* __restrict__ Wst,
                                                  const float* __restrict__ Wout) {
    __shared__ float sAt[16][68];
    __shared__ float sB[16][132];
    const int tid = threadIdx.x;
    const int tx = tid & 15, ty = tid >> 4;
    const int k = blockIdx.x;
    const int fbase = blockIdx.y * 64;
    float acc[4][8] = {};

    for (int fo = 0; fo < 64; fo += 16) {
        int f0 = fbase + fo;
        int ar = tid >> 2, ac = (tid & 3) * 4;
        float4 a = *(const float4*)&Wst[((size_t)k * DSUB + ar) * FDIM + f0 + ac];
        sAt[ac + 0][ar] = a.x; sAt[ac + 1][ar] = a.y;
        sAt[ac + 2][ar] = a.z; sAt[ac + 3][ar] = a.w;
        int bo = tid >> 1, bf = (tid & 1) * 8;
        const float* wpp = Wout + (size_t)bo * FDIM + f0 + bf;
        float4 b1 = *(const float4*)wpp;
        float4 b2 = *(const float4*)(wpp + 4);
        sB[bf + 0][bo] = b1.x; sB[bf + 1][bo] = b1.y;
        sB[bf + 2][bo] = b1.z; sB[bf + 3][bo] = b1.w;
        sB[bf + 4][bo] = b2.x; sB[bf + 5][bo] = b2.y;
        sB[bf + 6][bo] = b2.z; sB[bf + 7][bo] = b2.w;
        __syncthreads();
        #pragma unroll
        for (int kk = 0; kk < 16; kk++) {
            float ra[4], rb[8];
            *(float4*)&ra[0] = *(const float4*)&sAt[kk][ty * 4];
            *(float4*)&rb[0] = *(const float4*)&sB[kk][tx * 8];
            *(float4*)&rb[4] = *(const float4*)&sB[kk][tx * 8 + 4];
            #pragma unroll
            for (int i = 0; i < 4; i++)
                #pragma unroll
                for (int j = 0; j < 8; j++) acc[i][j] += ra[i] * rb[j];
        }
        __syncthreads();
    }
    #pragma unroll
    for (int i = 0; i < 4; i++) {
        int d = ty * 4 + i;
        *(float4*)&g_WWop[k][blockIdx.y][d][tx * 8]     = make_float4(acc[i][0], acc[i][1], acc[i][2], acc[i][3]);
        *(float4*)&g_WWop[k][blockIdx.y][d][tx * 8 + 4] = make_float4(acc[i][4], acc[i][5], acc[i][6], acc[i][7]);
    }
}

// ============================================================
// 6) chol_factor: loads pre-reduced M, blocked right-looking factor
// ============================================================
__global__ __launch_bounds__(256) void chol_factor(void) {
    __shared__ float sM[DSUB * 65];
    __shared__ float sD[DSUB];
    const int k = blockIdx.x, tid = threadIdx.x;
    const int lane = tid & 31;
    const int warp = tid >> 5;

    for (int idx = tid; idx < DSUB * DSUB; idx += 256) {
        int i = idx >> 6, j = idx & 63;
        sM[i * 65 + j] = g_G[k][idx];
    }
    __syncthreads();

    const int ui = tid >> 2;          // trailing-update row 0..63
    const int ub = tid & 3;           // trailing-update col base
    for (int p0 = 0; p0 < DSUB; p0 += 8) {
        if (warp == 0) {
            #pragma unroll
            for (int jj = 0; jj < 8; jj++) {
                const int j = p0 + jj;
                float d = sM[j * 65 + j];
                float dinv = rsqrtf(d);
                if (lane == 0) sD[j] = d;
                #pragma unroll
                for (int h = 0; h < 2; h++) {
                    int i = lane + h * 32;
                    if (i > j) sM[i * 65 + j] *= dinv;
                }
                __syncwarp();
                for (int p = j + 1; p < p0 + 8; p++) {
                    float cp = sM[p * 65 + j];
                    #pragma unroll
                    for (int h = 0; h < 2; h++) {
                        int i = lane + h * 32;
                        if (i >= p) sM[i * 65 + p] -= sM[i * 65 + j] * cp;
                    }
                    __syncwarp();
                }
                if (lane == 0) sM[j * 65 + j] = dinv;   // diag := 1/sqrt for solver
                __syncwarp();
            }
        }
        __syncthreads();
        const int p1 = p0 + 8;
        if (p1 < DSUB && ui >= p1) {
            float lrow[8];
            #pragma unroll
            for (int jj = 0; jj < 8; jj++) lrow[jj] = sM[ui * 65 + p0 + jj];
            #pragma unroll
            for (int qq = 0; qq < 16; qq++) {
                int c = ub + (qq << 2);
                if (c >= p1 && c <= ui) {
                    float s = 0.f;
                    #pragma unroll
                    for (int jj = 0; jj < 8; jj++)
                        s += lrow[jj] * sM[c * 65 + p0 + jj];
                    sM[ui * 65 + c] -= s;
                }
            }
        }
        __syncthreads();
    }

    if (tid == 0) {
        float r = 0.f;
        #pragma unroll 4
        for (int j = 0; j < DSUB; j++) r += logf(sD[j]);
        g_R[k] = 0.5f * r;
    }
    __syncthreads();
    for (int idx = tid; idx < DSUB * 65; idx += 256) g_Lf[k][idx] = sM[idx];
}

// ============================================================
// 7) finalize softmax weights + output tail
// ============================================================
__global__ void finalize_w(const float* __restrict__ taup, float* __restrict__ out_tail) {
    if (threadIdx.x != 0) return;
    float R0 = g_R[0], R1 = g_R[1], R2 = g_R[2];
    float d0 = R0, d1 = R1 - R0, d2 = R2 - R1;
    float mean = (d0 + d1 + d2) * (1.f / 3.f);
    float e0 = d0 - mean, e1 = d1 - mean, e2 = d2 - mean;
    float sd = sqrtf((e0 * e0 + e1 * e1 + e2 * e2) * 0.5f);   // ddof=1
    float s = 1.f / (sd + 1e-6f);
    float n0 = e0 * s, n1 = e1 * s, n2 = e2 * s;
    float tau = taup[0];
    float a0 = n0 / tau, a1 = n1 / tau, a2 = n2 / tau;
    float mx = fmaxf(a0, fmaxf(a1, a2));
    float x0 = expf(a0 - mx), x1 = expf(a1 - mx), x2 = expf(a2 - mx);
    float isum = 1.f / (x0 + x1 + x2);
    float w0 = x0 * isum, w1 = x1 * isum, w2 = x2 * isum;
    out_tail[0] = w0; out_tail[1] = w1; out_tail[2] = w2;
    out_tail[3] = n0; out_tail[4] = n1; out_tail[5] = n2;
    out_tail[6] = d0; out_tail[7] = d1; out_tail[8] = d2;
    g_s[0] = ETA_C * COEFF * w0;
    g_s[1] = ETA_C * COEFF * w1;
    g_s[2] = ETA_C * COEFF * w2;
}

// ============================================================
// 8) trisolve: Bs[k] = s_k * M^{-1} (sum WWop)   (128 RHS)
// ============================================================
#define TRI_SMEM ((DSUB * 65 + DSUB * 132) * 4)
__global__ __launch_bounds__(128) void trisolve_B(void) {
    extern __shared__ float tsm[];
    float* sL = tsm;                  // [64][65], diag = 1/sqrt
    float* sY = tsm + DSUB * 65;      // [64][132]
    const int k = blockIdx.x, c = threadIdx.x;

    for (int idx = c; idx < DSUB * 65; idx += 128) sL[idx] = g_Lf[k][idx];
    __syncthreads();

    const float sk = g_s[k];
    for (int i = 0; i < DSUB; i++) {
        float s = g_WWop[k][0][i][c] + g_WWop[k][1][i][c]
                + g_WWop[k][2][i][c] + g_WWop[k][3][i][c];
        float s0 = 0.f, s1 = 0.f, s2 = 0.f, s3 = 0.f;
        int j = 0;
        for (; j + 4 <= i; j += 4) {
            s0 += sL[i * 65 + j + 0] * sY[(j + 0) * 132 + c];
            s1 += sL[i * 65 + j + 1] * sY[(j + 1) * 132 + c];
            s2 += sL[i * 65 + j + 2] * sY[(j + 2) * 132 + c];
            s3 += sL[i * 65 + j + 3] * sY[(j + 3) * 132 + c];
        }
        for (; j < i; j++) s0 += sL[i * 65 + j] * sY[j * 132 + c];
        sY[i * 132 + c] = (s - ((s0 + s1) + (s2 + s3))) * sL[i * 65 + i];
    }
    for (int i = DSUB - 1; i >= 0; i--) {
        float s = sY[i * 132 + c];
        float s0 = 0.f, s1 = 0.f, s2 = 0.f, s3 = 0.f;
        int j = i + 1;
        for (; j + 4 <= DSUB; j += 4) {
            s0 += sL[(j + 0) * 65 + i] * sY[(j + 0) * 132 + c];
            s1 += sL[(j + 1) * 65 + i] * sY[(j + 1) * 132 + c];
            s2 += sL[(j + 2) * 65 + i] * sY[(j + 2) * 132 + c];
            s3 += sL[(j + 3) * 65 + i] * sY[(j + 3) * 132 + c];
        }
        for (; j < DSUB; j++) s0 += sL[j * 65 + i] * sY[j * 132 + c];
        float x = (s - ((s0 + s1) + (s2 + s3))) * sL[i * 65 + i];
        sY[i * 132 + c] = x;
        g_Bs[k][i][c] = sk * x;
    }
}

// ============================================================
// 9) H_pre = HW + sum_k Z_k @ Bs_k - 0.15*(LHWp0+LHWp1) ; soft-thr ; LN
// ============================================================
__global__ __launch_bounds__(256) void fuse_out(const float* __restrict__ thrP,
                                                const float* __restrict__ gamP,
                                                const float* __restrict__ betP,
                                                float* __restrict__ out) {
    __shared__ float sAt[16][68];   // Z chunk transposed [d][row]
    __shared__ float sB[16][132];   // Bs chunk [d][col]
    const int tid = threadIdx.x;
    const int tx = tid & 15, ty = tid >> 4;
    const int r0 = blockIdx.x * 64;
    float acc[4][8] = {};

    for (int k = 0; k < KHOP; k++) {
        for (int d0 = 0; d0 < DSUB; d0 += 16) {
            int ar = tid >> 2, ac = (tid & 3) * 4;
            float4 a = *(const float4*)&g_Z[k][r0 + ar][d0 + ac];
            sAt[ac + 0][ar] = a.x; sAt[ac + 1][ar] = a.y;
            sAt[ac + 2][ar] = a.z; sAt[ac + 3][ar] = a.w;
            int dl = tid >> 4, c8 = (tid & 15) * 8;
            float4 b1 = *(const float4*)&g_Bs[k][d0 + dl][c8];
            float4 b2 = *(const float4*)&g_Bs[k][d0 + dl][c8 + 4];
            *(float4*)&sB[dl][c8]     = b1;
            *(float4*)&sB[dl][c8 + 4] = b2;
            __syncthreads();
            #pragma unroll
            for (int kk = 0; kk < 16; kk++) {
                float ra[4], rb[8];
                *(float4*)&ra[0] = *(const float4*)&sAt[kk][ty * 4];
                *(float4*)&rb[0] = *(const float4*)&sB[kk][tx * 8];
                *(float4*)&rb[4] = *(const float4*)&sB[kk][tx * 8 + 4];
                #pragma unroll
                for (int i = 0; i < 4; i++)
                    #pragma unroll
                    for (int j = 0; j < 8; j++) acc[i][j] += ra[i] * rb[j];
            }
            __syncthreads();
        }
    }

    float thr_[8], gam_[8], bet_[8];
    #pragma unroll
    for (int j = 0; j < 8; j++) {
        int c = tx * 8 + j;
        thr_[j] = fabsf(__ldg(&thrP[c]));
        gam_[j] = __ldg(&gamP[c]);
        bet_[j] = __ldg(&betP[c]);
    }
    #pragma unroll
    for (int i = 0; i < 4; i++) {
        size_t row = r0 + ty * 4 + i;
        float4 hw1 = *(const float4*)&g_HW[row * ODIM + tx * 8];
        float4 hw2 = *(const float4*)&g_HW[row * ODIM + tx * 8 + 4];
        float4 p1a = *(const float4*)&g_LHWp[0][row * ODIM + tx * 8];
        float4 p1b = *(const float4*)&g_LHWp[0][row * ODIM + tx * 8 + 4];
        float4 p2a = *(const float4*)&g_LHWp[1][row * ODIM + tx * 8];
        float4 p2b = *(const float4*)&g_LHWp[1][row * ODIM + tx * 8 + 4];
        float bias[8] = {hw1.x - LAPSC * (p1a.x + p2a.x), hw1.y - LAPSC * (p1a.y + p2a.y),
                         hw1.z - LAPSC * (p1a.z + p2a.z), hw1.w - LAPSC * (p1a.w + p2a.w),
                         hw2.x - LAPSC * (p1b.x + p2b.x), hw2.y - LAPSC * (p1b.y + p2b.y),
                         hw2.z - LAPSC * (p1b.z + p2b.z), hw2.w - LAPSC * (p1b.w + p2b.w)};
        float v[8], s = 0.f, q = 0.f;
        #pragma unroll
        for (int j = 0; j < 8; j++) {
            float p = acc[i][j] + bias[j];
            float ap = fabsf(p) - thr_[j];
            float val = ap > 0.f ? copysignf(ap, p) : 0.f;
            v[j] = val; s += val; q += val * val;
        }
        #pragma unroll
        for (int o = 8; o >= 1; o >>= 1) {
            s += __shfl_xor_sync(0xffffffffu, s, o);
            q += __shfl_xor_sync(0xffffffffu, q, o);
        }
        float mu = s * (1.f / 128.f);
        float var = q * (1.f / 128.f) - mu * mu;
        float rs = rsqrtf(var + LN_EPSF);
        float o_[8];
        #pragma unroll
        for (int j = 0; j < 8; j++) o_[j] = (v[j] - mu) * rs * gam_[j] + bet_[j];
        *(float4*)&out[row * ODIM + tx * 8]     = make_float4(o_[0], o_[1], o_[2], o_[3]);
        *(float4*)&out[row * ODIM + tx * 8 + 4] = make_float4(o_[4], o_[5], o_[6], o_[7]);
    }
}

// ============================================================
extern "C" void kernel_launch(void* const* d_in, const int* in_sizes, int n_in,
                              void* d_out, int out_size) {
    const float* H    = (const float*)d_in[0];
    const float* hop  = (const float*)d_in[1];
    const float* L    = (const float*)d_in[2];
    const float* Wst  = (const float*)d_in[3];
    const float* Wout = (const float*)d_in[4];
    const float* thr  = (const float*)d_in[5];
    const float* gam  = (const float*)d_in[6];
    const float* bet  = (const float*)d_in[7];
    const float* tau  = (const float*)d_in[8];
    float* out = (float*)d_out;
    float* out_tail = out + (size_t)NN * ODIM;

    float* d_HW;
    cudaGetSymbolAddress((void**)&d_HW, g_HW);
    float* d_LHWp;
    cudaGetSymbolAddress((void**)&d_LHWp, g_LHWp);

    cudaFuncSetAttribute(trisolve_B, cudaFuncAttributeMaxDynamicSharedMemorySize, TRI_SMEM);
    cudaFuncSetAttribute(gemmLHW,    cudaFuncAttributeMaxDynamicSharedMemorySize, G2_SMEM);

    // ---- fork: spine B (Z/G/reduce/WWo/chol/finalize/trisolve) on side stream ----
    cudaEventRecord(g_sr.evFork, 0);
    cudaStreamWaitEvent(g_sr.s2, g_sr.evFork, 0);

    compute_Z<<<dim3(128, KHOP), 256, 0, g_sr.s2>>>(hop, Wst);
    compute_G<<<dim3(32, KHOP), 256, 0, g_sr.s2>>>();
    reduce_G<<<dim3(KHOP, 16), 256, 0, g_sr.s2>>>();
    computeWWo<<<dim3(KHOP, 4), 256, 0, g_sr.s2>>>(Wst, Wout);
    chol_factor<<<KHOP, 256, 0, g_sr.s2>>>();
    finalize_w<<<1, 32, 0, g_sr.s2>>>(tau, out_tail);
    trisolve_B<<<KHOP, 128, TRI_SMEM, g_sr.s2>>>();
    cudaEventRecord(g_sr.evJoin, g_sr.s2);

    // ---- spine A (HW -> big gemm) on main stream ----
    computeHW<<<128, 256>>>(H, Wout);
    gemmLHW<<<dim3(2, 128), 256, G2_SMEM>>>(L, d_HW, d_LHWp);

    // ---- join, then fused epilogue ----
    cudaStreamWaitEvent(0, g_sr.evJoin, 0);
    fuse_out<<<128, 256>>>(thr, gam, bet, out);
}